// round 14
// baseline (speedup 1.0000x reference)
#include <cuda_runtime.h>
#include <cuda_fp16.h>
#include <math.h>
#include <cstddef>
#include <cstdint>

// ---------------- problem constants ----------------
#define B_    4096
#define DIN   512
#define DH    1024
#define DOUT  256
#define DFF   4096
#define STEPS 30
#define LN_EPSF 1e-5f
#define GAMMA_F 0.17677669529663687f   // 0.5*sqrt(64/512)
#define NSM   148

// ---------------- device scratch (no allocations allowed) ----------------
__device__ float g_xemb[(size_t)B_ * DH];   // also scratch: V^T (16MB) during spectral
__device__ float g_hA[(size_t)B_ * DH];     // also scratch: Gram B (4MB) during spectral
__device__ float g_hB[(size_t)B_ * DH];
__device__ __half g_W1h[(size_t)DFF * DH];
__device__ __half g_W2h[(size_t)DH * DFF];
__device__ __half g_hn[(size_t)B_ * DH];
__device__ __half g_hid[(size_t)B_ * DFF];  // also scratch: Vhi/Vlo during spectral
__device__ float g_u[4096];
__device__ float g_v0[4096];
__device__ float g_v1[4096];
__device__ float g_t[4096];
__device__ float g_sig[2];
__device__ float g_ssum[B_];
__device__ float g_sss[B_];
__device__ float g_ctr[1];

// ---------------- low-level helpers (plain sm_80+ features only) ----------------
__device__ __forceinline__ uint32_t smem_u32(const void* p) {
    uint32_t a;
    asm("{ .reg .u64 t; cvta.to.shared.u64 t, %1; cvt.u32.u64 %0, t; }" : "=r"(a) : "l"(p));
    return a;
}
__device__ __forceinline__ void cp_async16(uint32_t dst, const void* src) {
    asm volatile("cp.async.cg.shared.global [%0], [%1], 16;" :: "r"(dst), "l"(src) : "memory");
}
__device__ __forceinline__ void cp_commit() {
    asm volatile("cp.async.commit_group;" ::: "memory");
}
template<int N> __device__ __forceinline__ void cp_wait() {
    asm volatile("cp.async.wait_group %0;" :: "n"(N) : "memory");
}
__device__ __forceinline__ void ldm_x4(uint32_t addr, uint32_t* r) {
    asm volatile("ldmatrix.sync.aligned.m8n8.x4.shared.b16 {%0,%1,%2,%3}, [%4];"
        : "=r"(r[0]), "=r"(r[1]), "=r"(r[2]), "=r"(r[3]) : "r"(addr));
}
__device__ __forceinline__ void mma_f16(float* d, const uint32_t* a, const uint32_t* b) {
    asm volatile("mma.sync.aligned.m16n8k16.row.col.f32.f16.f16.f32 "
        "{%0,%1,%2,%3}, {%4,%5,%6,%7}, {%8,%9}, {%0,%1,%2,%3};"
        : "+f"(d[0]), "+f"(d[1]), "+f"(d[2]), "+f"(d[3])
        : "r"(a[0]), "r"(a[1]), "r"(a[2]), "r"(a[3]), "r"(b[0]), "r"(b[1]));
}
__device__ __forceinline__ float tanh_fast(float x) {
    float y;
    asm("tanh.approx.f32 %0, %1;" : "=f"(y) : "f"(x));
    return y;
}
__device__ __forceinline__ uint32_t sw_off(int r, int c) {
    return ((uint32_t)r << 6) + (uint32_t)((c ^ ((r >> 1) & 3)) << 4);
}

// ---------------- small kernels ----------------
__global__ void init_vec_kernel(float* v, size_t n, float val) {
    size_t i = (size_t)blockIdx.x * blockDim.x + threadIdx.x;
    if (i < n) v[i] = val;
}

// out[C][R] = in[R][C]^T, 32x32 tiles, 256 threads
__global__ void transpose_kernel(const float* __restrict__ in, float* __restrict__ out,
                                 int R, int C) {
    __shared__ float tile[32][33];
    int tx = threadIdx.x & 31, ty = threadIdx.x >> 5;
    int bx = blockIdx.x * 32;
    int by = blockIdx.y * 32;
    #pragma unroll
    for (int p = 0; p < 4; p++)
        tile[ty + p * 8][tx] = in[(size_t)(by + ty + p * 8) * C + bx + tx];
    __syncthreads();
    #pragma unroll
    for (int p = 0; p < 4; p++)
        out[(size_t)(bx + ty + p * 8) * R + by + tx] = tile[tx][ty + p * 8];
}

// fp32 -> fp16 hi/lo split (float4 loads)
__global__ void split_hilo(const float* __restrict__ in,
                           __half* __restrict__ hi, __half* __restrict__ lo, size_t n) {
    size_t n4 = n >> 2;
    size_t stride = (size_t)gridDim.x * blockDim.x;
    const float4* in4 = reinterpret_cast<const float4*>(in);
    for (size_t i = (size_t)blockIdx.x * blockDim.x + threadIdx.x; i < n4; i += stride) {
        float4 w = in4[i];
        __half h0 = __float2half_rn(w.x), h1 = __float2half_rn(w.y);
        __half h2 = __float2half_rn(w.z), h3 = __float2half_rn(w.w);
        __half2 a, b, c, d;
        a.x = h0; a.y = h1; b.x = h2; b.y = h3;
        c.x = __float2half_rn(w.x - __half2float(h0));
        c.y = __float2half_rn(w.y - __half2float(h1));
        d.x = __float2half_rn(w.z - __half2float(h2));
        d.y = __float2half_rn(w.w - __half2float(h3));
        *reinterpret_cast<__half2*>(hi + i * 4)     = a;
        *reinterpret_cast<__half2*>(hi + i * 4 + 2) = b;
        *reinterpret_cast<__half2*>(lo + i * 4)     = c;
        *reinterpret_cast<__half2*>(lo + i * 4 + 2) = d;
    }
}

// y[row] = dot(W[row,:], v)
__global__ void matvec_rows(const float* __restrict__ W, const float* __restrict__ v,
                            float* __restrict__ y, int C) {
    int row = blockIdx.x;
    const float4* Wr = reinterpret_cast<const float4*>(W + (size_t)row * C);
    const float4* v4 = reinterpret_cast<const float4*>(v);
    int C4 = C >> 2;
    float acc = 0.f;
    for (int j = threadIdx.x; j < C4; j += 256) {
        float4 a = Wr[j];
        float4 b = v4[j];
        acc += a.x * b.x + a.y * b.y + a.z * b.z + a.w * b.w;
    }
    __shared__ float sm[8];
    #pragma unroll
    for (int o = 16; o > 0; o >>= 1) acc += __shfl_down_sync(0xffffffffu, acc, o);
    if ((threadIdx.x & 31) == 0) sm[threadIdx.x >> 5] = acc;
    __syncthreads();
    if (threadIdx.x < 8) {
        float a = sm[threadIdx.x];
        #pragma unroll
        for (int o = 4; o > 0; o >>= 1) a += __shfl_down_sync(0xffu, a, o);
        if (threadIdx.x == 0) y[row] = a;
    }
}

// y = B @ x, B [n,n] fp32 (L2-resident). 8 rows/block, warp per row.
__global__ void bmatvec(const float* __restrict__ B, const float* __restrict__ x,
                        float* __restrict__ y, int n) {
    int row = blockIdx.x * 8 + (threadIdx.x >> 5);
    int lane = threadIdx.x & 31;
    const float4* Br = reinterpret_cast<const float4*>(B + (size_t)row * n);
    const float4* x4 = reinterpret_cast<const float4*>(x);
    int n4 = n >> 2;
    float acc = 0.f;
    for (int j = lane; j < n4; j += 32) {
        float4 a = Br[j], b = x4[j];
        acc += a.x * b.x + a.y * b.y + a.z * b.z + a.w * b.w;
    }
    #pragma unroll
    for (int o = 16; o > 0; o >>= 1) acc += __shfl_down_sync(0xffffffffu, acc, o);
    if (lane == 0) y[row] = acc;
}

// sigma = sqrt( (q.q) / (p.q) )
__global__ void sigma_pq(const float* __restrict__ p, const float* __restrict__ q,
                         int n, float* __restrict__ sig) {
    float qq = 0.f, pq = 0.f;
    for (int i = threadIdx.x; i < n; i += 1024) {
        float qi = q[i];
        qq += qi * qi;
        pq += p[i] * qi;
    }
    __shared__ float s1[32], s2[32];
    #pragma unroll
    for (int o = 16; o > 0; o >>= 1) {
        qq += __shfl_down_sync(0xffffffffu, qq, o);
        pq += __shfl_down_sync(0xffffffffu, pq, o);
    }
    if ((threadIdx.x & 31) == 0) { s1[threadIdx.x >> 5] = qq; s2[threadIdx.x >> 5] = pq; }
    __syncthreads();
    if (threadIdx.x < 32) {
        float a = s1[threadIdx.x], b = s2[threadIdx.x];
        #pragma unroll
        for (int o = 16; o > 0; o >>= 1) {
            a += __shfl_down_sync(0xffffffffu, a, o);
            b += __shfl_down_sync(0xffffffffu, b, o);
        }
        if (threadIdx.x == 0) sig[0] = sqrtf(a / b);
    }
}

// sigma = sqrt( (a.b) / (c.b) )
__global__ void sigma_cab(const float* __restrict__ c, const float* __restrict__ a,
                          const float* __restrict__ b, int n, float* __restrict__ sig) {
    float ab = 0.f, cb = 0.f;
    for (int i = threadIdx.x; i < n; i += 1024) {
        float bi = b[i];
        ab += a[i] * bi;
        cb += c[i] * bi;
    }
    __shared__ float s1[32], s2[32];
    #pragma unroll
    for (int o = 16; o > 0; o >>= 1) {
        ab += __shfl_down_sync(0xffffffffu, ab, o);
        cb += __shfl_down_sync(0xffffffffu, cb, o);
    }
    if ((threadIdx.x & 31) == 0) { s1[threadIdx.x >> 5] = ab; s2[threadIdx.x >> 5] = cb; }
    __syncthreads();
    if (threadIdx.x < 32) {
        float x = s1[threadIdx.x], y = s2[threadIdx.x];
        #pragma unroll
        for (int o = 16; o > 0; o >>= 1) {
            x += __shfl_down_sync(0xffffffffu, x, o);
            y += __shfl_down_sync(0xffffffffu, y, o);
        }
        if (threadIdx.x == 0) sig[0] = sqrtf(x / y);
    }
}

// Wh = fp16(W / sigma)
__global__ void scale_half(const float* __restrict__ W, const float* __restrict__ sig,
                           __half* __restrict__ Wh, size_t n) {
    float inv = 1.0f / sig[0];
    size_t n4 = n >> 2;
    size_t stride = (size_t)gridDim.x * blockDim.x;
    const float4* W4 = reinterpret_cast<const float4*>(W);
    for (size_t i = (size_t)blockIdx.x * blockDim.x + threadIdx.x; i < n4; i += stride) {
        float4 w = W4[i];
        __half2 a, b;
        a.x = __float2half_rn(w.x * inv); a.y = __float2half_rn(w.y * inv);
        b.x = __float2half_rn(w.z * inv); b.y = __float2half_rn(w.w * inv);
        *reinterpret_cast<__half2*>(Wh + i * 4)     = a;
        *reinterpret_cast<__half2*>(Wh + i * 4 + 2) = b;
    }
}

// ---------------- standalone layernorm (h0 only): fp32 in, fp16 out ----------------
__global__ void layernorm_half(const float* __restrict__ h,
                               const float* __restrict__ g, const float* __restrict__ b,
                               __half* __restrict__ o) {
    int row = blockIdx.x;
    const float* hr = h + (size_t)row * DH;
    float s = 0.f, ss = 0.f;
    float xl[4];
    #pragma unroll
    for (int t = 0; t < 4; t++) {
        float x = hr[threadIdx.x + t * 256];
        xl[t] = x; s += x; ss += x * x;
    }
    __shared__ float sm1[8], sm2[8];
    #pragma unroll
    for (int o2 = 16; o2 > 0; o2 >>= 1) {
        s  += __shfl_down_sync(0xffffffffu, s, o2);
        ss += __shfl_down_sync(0xffffffffu, ss, o2);
    }
    if ((threadIdx.x & 31) == 0) { sm1[threadIdx.x >> 5] = s; sm2[threadIdx.x >> 5] = ss; }
    __syncthreads();
    __shared__ float s_mu, s_inv;
    if (threadIdx.x < 8) {
        float a = sm1[threadIdx.x], c = sm2[threadIdx.x];
        #pragma unroll
        for (int o2 = 4; o2 > 0; o2 >>= 1) {
            a += __shfl_down_sync(0xffu, a, o2);
            c += __shfl_down_sync(0xffu, c, o2);
        }
        if (threadIdx.x == 0) {
            float mu  = a * (1.0f / DH);
            float var = c * (1.0f / DH) - mu * mu;
            s_mu = mu; s_inv = rsqrtf(var + LN_EPSF);
        }
    }
    __syncthreads();
    float mu = s_mu, inv = s_inv;
    #pragma unroll
    for (int t = 0; t < 4; t++) {
        int j = threadIdx.x + t * 256;
        float y = (xl[t] - mu) * inv * g[j] + b[j];
        o[(size_t)row * DH + j] = __float2half_rn(y);
    }
}

// ---------------- Gram kernel (spectral): 3-term hi/lo, split-K, atomic accum ----
#define G_MST   4
#define G_ATILE 16384
#define G_WTILE 8192
#define G_STAGE (2 * G_ATILE + 2 * G_WTILE)
#define G_SMEM  (G_MST * G_STAGE)

__device__ __forceinline__ void gram_load_stage(
    uint32_t sbase, int buf, int k0,
    const __half* __restrict__ Vhi, const __half* __restrict__ Vlo,
    int bm, int bn, int K, int tid)
{
    uint32_t base = sbase + (uint32_t)buf * G_STAGE;
    #pragma unroll
    for (int j = 0; j < 8; j++) {
        int c = tid + j * 256;
        int part = c >> 10;
        int rr = (c & 1023) >> 2, c16 = c & 3;
        const __half* g = part ? Vlo : Vhi;
        cp_async16(base + (uint32_t)part * G_ATILE + sw_off(rr, c16),
                   g + (size_t)(bm + rr) * K + k0 + c16 * 8);
    }
    #pragma unroll
    for (int j = 0; j < 4; j++) {
        int c = tid + j * 256;
        int part = c >> 9;
        int rr = (c & 511) >> 2, c16 = c & 3;
        const __half* g = part ? Vlo : Vhi;
        cp_async16(base + 2u * G_ATILE + (uint32_t)part * G_WTILE + sw_off(rr, c16),
                   g + (size_t)(bn + rr) * K + k0 + c16 * 8);
    }
}

__global__ __launch_bounds__(256, 1) void gram_f16x3(
    const __half* __restrict__ Vhi, const __half* __restrict__ Vlo,
    float* __restrict__ G, int N, int K, int nunits, int nx, int kchunks)
{
    extern __shared__ __align__(128) char smem[];
    uint32_t sb = smem_u32(smem);
    int tid = threadIdx.x, wid = tid >> 5, lane = tid & 31;
    int m0 = (wid >> 1) * 64, n0 = (wid & 1) * 64;
    int r16 = lane & 15, kh = lane >> 4;
    int g8 = lane >> 3, l8 = lane & 7;
    int qr = lane >> 2, qc = (lane & 3) * 2;

    for (int unit = blockIdx.x; unit < nunits; unit += gridDim.x) {
        int tile = unit >> 2, kid = unit & 3;
        int bm = (tile / nx) * 256, bn = (tile % nx) * 128;
        int kbase = kid * (kchunks << 5);

        float acc[4][8][4] = {};

        #pragma unroll
        for (int s = 0; s < G_MST - 1; s++) {
            gram_load_stage(sb, s, kbase + (s << 5), Vhi, Vlo, bm, bn, K, tid);
            cp_commit();
        }

        for (int i = 0; i < kchunks; i++) {
            cp_wait<G_MST - 2>();
            __syncthreads();

            uint32_t st = sb + (uint32_t)(i & (G_MST - 1)) * G_STAGE;
            #pragma unroll
            for (int ks = 0; ks < 2; ks++) {
                uint32_t a_hi[4][4], a_lo[4][4], w_hi[4][4], w_lo[4][4];
                #pragma unroll
                for (int mt = 0; mt < 4; mt++) {
                    uint32_t ar = st + sw_off(m0 + mt * 16 + r16, ks * 2 + kh);
                    ldm_x4(ar, a_hi[mt]);
                    ldm_x4(ar + G_ATILE, a_lo[mt]);
                }
                #pragma unroll
                for (int nh = 0; nh < 4; nh++) {
                    uint32_t br = st + 2 * G_ATILE +
                        sw_off(n0 + nh * 16 + (g8 >> 1) * 8 + l8, ks * 2 + (g8 & 1));
                    ldm_x4(br, w_hi[nh]);
                    ldm_x4(br + G_WTILE, w_lo[nh]);
                }
                #pragma unroll
                for (int mt = 0; mt < 4; mt++)
                    #pragma unroll
                    for (int nt = 0; nt < 8; nt++)
                        mma_f16(acc[mt][nt], a_hi[mt], &w_hi[nt >> 1][(nt & 1) * 2]);
                #pragma unroll
                for (int mt = 0; mt < 4; mt++)
                    #pragma unroll
                    for (int nt = 0; nt < 8; nt++)
                        mma_f16(acc[mt][nt], a_hi[mt], &w_lo[nt >> 1][(nt & 1) * 2]);
                #pragma unroll
                for (int mt = 0; mt < 4; mt++)
                    #pragma unroll
                    for (int nt = 0; nt < 8; nt++)
                        mma_f16(acc[mt][nt], a_lo[mt], &w_hi[nt >> 1][(nt & 1) * 2]);
            }

            int nxt = i + G_MST - 1;
            if (nxt < kchunks)
                gram_load_stage(sb, nxt & (G_MST - 1), kbase + (nxt << 5), Vhi, Vlo, bm, bn, K, tid);
            cp_commit();
        }

        #pragma unroll
        for (int mt = 0; mt < 4; mt++) {
            #pragma unroll
            for (int nt = 0; nt < 8; nt++) {
                int c0 = bn + n0 + nt * 8 + qc;
                #pragma unroll
                for (int h = 0; h < 2; h++) {
                    int r = bm + m0 + mt * 16 + qr + h * 8;
                    size_t idx = (size_t)r * N + c0;
                    atomicAdd(&G[idx],     acc[mt][nt][h * 2 + 0]);
                    atomicAdd(&G[idx + 1], acc[mt][nt][h * 2 + 1]);
                }
            }
        }
        __syncthreads();
    }
}

// ---------------- fp16 single-term persistent GEMM (shared pieces) ----------------
#define MSTAGES 4
#define ATILEB  (256 * 64)
#define WTILEB  (128 * 64)
#define STAGEB  (ATILEB + WTILEB)
#define GSMEM   (MSTAGES * STAGEB)       // 98304 B

__device__ __forceinline__ void load_stage(
    uint32_t sbase, int buf, int k0,
    const __half* __restrict__ A, const __half* __restrict__ Wh,
    int bm, int bn, int K, int tid)
{
    uint32_t base = sbase + (uint32_t)buf * STAGEB;
    #pragma unroll
    for (int j = 0; j < 4; j++) {
        int c = tid + j * 256;
        int rr = c >> 2, c16 = c & 3;
        cp_async16(base + sw_off(rr, c16),
                   A + (size_t)(bm + rr) * K + k0 + c16 * 8);
    }
    #pragma unroll
    for (int j = 0; j < 2; j++) {
        int c = tid + j * 256;
        int rr = c >> 2, c16 = c & 3;
        cp_async16(base + (uint32_t)ATILEB + sw_off(rr, c16),
                   Wh + (size_t)(bn + rr) * K + k0 + c16 * 8);
    }
}

// GEMM1: hid = tanh(hn @ W1^T + b1), fp16 out
__global__ __launch_bounds__(256, 1) void gemm_tanh(
    const __half* __restrict__ A, const __half* __restrict__ Wh,
    const float* __restrict__ bias, int N, int K, int ntiles, int nx,
    __half* __restrict__ Ch) {

    extern __shared__ __align__(128) char smem[];
    uint32_t sb = smem_u32(smem);
    int tid = threadIdx.x, wid = tid >> 5, lane = tid & 31;
    int m0 = (wid >> 1) * 64, n0 = (wid & 1) * 64;
    int r16 = lane & 15, kh = lane >> 4;
    int g8 = lane >> 3, l8 = lane & 7;
    int qr = lane >> 2, qc = (lane & 3) * 2;
    const int nch = K >> 5;

    for (int tile = blockIdx.x; tile < ntiles; tile += gridDim.x) {
        int bm = (tile / nx) * 256, bn = (tile % nx) * 128;

        float acc[4][8][4] = {};

        #pragma unroll
        for (int s = 0; s < MSTAGES - 1; s++) {
            load_stage(sb, s, s << 5, A, Wh, bm, bn, K, tid);
            cp_commit();
        }

        for (int i = 0; i < nch; i++) {
            cp_wait<MSTAGES - 2>();
            __syncthreads();

            uint32_t st = sb + (uint32_t)(i & (MSTAGES - 1)) * STAGEB;
            #pragma unroll
            for (int ks = 0; ks < 2; ks++) {
                uint32_t a[4][4], w[4][4];
                #pragma unroll
                for (int mt = 0; mt < 4; mt++)
                    ldm_x4(st + sw_off(m0 + mt * 16 + r16, ks * 2 + kh), a[mt]);
                #pragma unroll
                for (int nh = 0; nh < 4; nh++)
                    ldm_x4(st + ATILEB +
                           sw_off(n0 + nh * 16 + (g8 >> 1) * 8 + l8, ks * 2 + (g8 & 1)),
                           w[nh]);
                #pragma unroll
                for (int mt = 0; mt < 4; mt++)
                    #pragma unroll
                    for (int nt = 0; nt < 8; nt++)
                        mma_f16(acc[mt][nt], a[mt], &w[nt >> 1][(nt & 1) * 2]);
            }

            int nxt = i + MSTAGES - 1;
            if (nxt < nch)
                load_stage(sb, nxt & (MSTAGES - 1), nxt << 5, A, Wh, bm, bn, K, tid);
            cp_commit();
        }

        #pragma unroll
        for (int mt = 0; mt < 4; mt++) {
            #pragma unroll
            for (int nt = 0; nt < 8; nt++) {
                int c0 = bn + n0 + nt * 8 + qc;
                float2 bz = *(const float2*)(bias + c0);
                #pragma unroll
                for (int h = 0; h < 2; h++) {
                    int r = bm + m0 + mt * 16 + qr + h * 8;
                    float v0 = acc[mt][nt][h * 2 + 0] + bz.x;
                    float v1 = acc[mt][nt][h * 2 + 1] + bz.y;
                    size_t idx = (size_t)r * N + c0;
                    __half2 hp;
                    hp.x = __float2half_rn(tanh_fast(v0));
                    hp.y = __float2half_rn(tanh_fast(v1));
                    *(__half2*)(Ch + idx) = hp;
                }
            }
        }
        __syncthreads();
    }
}

// GEMM2 fused: h_next = (1-g)h + g(hid@W2^T + b2 + xemb), + per-row stats,
// grid barrier, then LN of h_next -> hn (fp16). Persistent, grid must = NSM.
__global__ __launch_bounds__(256, 1) void gemm_step_ln(
    const __half* __restrict__ A, const __half* __restrict__ Wh,
    const float* __restrict__ bias, int N, int K, int ntiles, int nx,
    float* __restrict__ Cf,
    const float* __restrict__ hprev, const float* __restrict__ xemb, float gamma,
    float* __restrict__ ssum, float* __restrict__ sss, float* __restrict__ ctr,
    int step, const float* __restrict__ lng, const float* __restrict__ lnb,
    __half* __restrict__ hn) {

    extern __shared__ __align__(128) char smem[];
    uint32_t sb = smem_u32(smem);
    int tid = threadIdx.x, wid = tid >> 5, lane = tid & 31;
    int m0 = (wid >> 1) * 64, n0 = (wid & 1) * 64;
    int r16 = lane & 15, kh = lane >> 4;
    int g8 = lane >> 3, l8 = lane & 7;
    int qr = lane >> 2, qc = (lane & 3) * 2;
    const int nch = K >> 5;

    // ---- phase 1: GEMM + step mix + per-row stats ----
    for (int tile = blockIdx.x; tile < ntiles; tile += gridDim.x) {
        int bm = (tile / nx) * 256, bn = (tile % nx) * 128;

        float acc[4][8][4] = {};

        #pragma unroll
        for (int s = 0; s < MSTAGES - 1; s++) {
            load_stage(sb, s, s << 5, A, Wh, bm, bn, K, tid);
            cp_commit();
        }

        for (int i = 0; i < nch; i++) {
            cp_wait<MSTAGES - 2>();
            __syncthreads();

            uint32_t st = sb + (uint32_t)(i & (MSTAGES - 1)) * STAGEB;
            #pragma unroll
            for (int ks = 0; ks < 2; ks++) {
                uint32_t a[4][4], w[4][4];
                #pragma unroll
                for (int mt = 0; mt < 4; mt++)
                    ldm_x4(st + sw_off(m0 + mt * 16 + r16, ks * 2 + kh), a[mt]);
                #pragma unroll
                for (int nh = 0; nh < 4; nh++)
                    ldm_x4(st + ATILEB +
                           sw_off(n0 + nh * 16 + (g8 >> 1) * 8 + l8, ks * 2 + (g8 & 1)),
                           w[nh]);
                #pragma unroll
                for (int mt = 0; mt < 4; mt++)
                    #pragma unroll
                    for (int nt = 0; nt < 8; nt++)
                        mma_f16(acc[mt][nt], a[mt], &w[nt >> 1][(nt & 1) * 2]);
            }

            int nxt = i + MSTAGES - 1;
            if (nxt < nch)
                load_stage(sb, nxt & (MSTAGES - 1), nxt << 5, A, Wh, bm, bn, K, tid);
            cp_commit();
        }

        float rs[4][2] = {}, rq[4][2] = {};
        #pragma unroll
        for (int mt = 0; mt < 4; mt++) {
            #pragma unroll
            for (int nt = 0; nt < 8; nt++) {
                int c0 = bn + n0 + nt * 8 + qc;
                float2 bz = *(const float2*)(bias + c0);
                #pragma unroll
                for (int h = 0; h < 2; h++) {
                    int r = bm + m0 + mt * 16 + qr + h * 8;
                    float v0 = acc[mt][nt][h * 2 + 0] + bz.x;
                    float v1 = acc[mt][nt][h * 2 + 1] + bz.y;
                    size_t idx = (size_t)r * N + c0;
                    float2 hp = *(const float2*)(hprev + idx);
                    float2 xe = *(const float2*)(xemb + idx);
                    float2 o;
                    o.x = (1.0f - gamma) * hp.x + gamma * (v0 + xe.x);
                    o.y = (1.0f - gamma) * hp.y + gamma * (v1 + xe.y);
                    *(float2*)(Cf + idx) = o;
                    rs[mt][h] += o.x + o.y;
                    rq[mt][h] += o.x * o.x + o.y * o.y;
                }
            }
        }
        // reduce across the 4 same-row lanes (qc groups), then atomics
        #pragma unroll
        for (int mt = 0; mt < 4; mt++) {
            #pragma unroll
            for (int h = 0; h < 2; h++) {
                float a = rs[mt][h], q = rq[mt][h];
                a += __shfl_xor_sync(0xffffffffu, a, 1);
                a += __shfl_xor_sync(0xffffffffu, a, 2);
                q += __shfl_xor_sync(0xffffffffu, q, 1);
                q += __shfl_xor_sync(0xffffffffu, q, 2);
                if ((lane & 3) == 0) {
                    int r = bm + m0 + mt * 16 + qr + h * 8;
                    atomicAdd(&ssum[r], a);
                    atomicAdd(&sss[r], q);
                }
            }
        }
        __syncthreads();
    }

    // ---- grid barrier ----
    __threadfence();
    __syncthreads();
    if (tid == 0) {
        float target = (float)((step + 1) * NSM);
        atomicAdd(ctr, 1.0f);
        while (atomicAdd(ctr, 0.0f) < target) { }
    }
    __syncthreads();

    // ---- phase 2: LN of h_next (L2-hot) -> hn, then zero own stat rows ----
    for (int r = blockIdx.x; r < B_; r += gridDim.x) {
        float mu  = ssum[r] * (1.0f / DH);
        float var = sss[r] * (1.0f / DH) - mu * mu;
        float inv = rsqrtf(var + LN_EPSF);
        float4 xv = reinterpret_cast<const float4*>(Cf + (size_t)r * DH)[tid];
        float4 gv = reinterpret_cast<const float4*>(lng)[tid];
        float4 bv = reinterpret_cast<const float4*>(lnb)[tid];
        __half2 o0, o1;
        o0.x = __float2half_rn((xv.x - mu) * inv * gv.x + bv.x);
        o0.y = __float2half_rn((xv.y - mu) * inv * gv.y + bv.y);
        o1.x = __float2half_rn((xv.z - mu) * inv * gv.z + bv.z);
        o1.y = __float2half_rn((xv.w - mu) * inv * gv.w + bv.w);
        *reinterpret_cast<__half2*>(hn + (size_t)r * DH + tid * 4)     = o0;
        *reinterpret_cast<__half2*>(hn + (size_t)r * DH + tid * 4 + 2) = o1;
        __syncthreads();
        if (tid == 0) { ssum[r] = 0.f; sss[r] = 0.f; }
    }
}

// ---------------- fp32 SIMT GEMM (embed + head only) ----------------
#define BM 128
#define BN 128
#define BK 8
#define TM 8
#define TN 8

__global__ __launch_bounds__(256, 2) void gemm_f32_bias(
    const float* __restrict__ A, const float* __restrict__ W,
    const float* __restrict__ bias, float* __restrict__ C,
    int M, int N, int K) {

    __shared__ __align__(16) float As[BK][BM];
    __shared__ __align__(16) float Ws[BK][BN];

    int tid = threadIdx.x;
    int bm = blockIdx.y * BM, bn = blockIdx.x * BN;
    const float* Ablk = A + (size_t)bm * K;
    const float* Wblk = W + (size_t)bn * K;

    int lrow = tid >> 1;
    int lcol = (tid & 1) * 4;
    int ty = tid >> 4, tx = tid & 15;

    float acc[TM][TN] = {};

    for (int k0 = 0; k0 < K; k0 += BK) {
        float4 a4 = *reinterpret_cast<const float4*>(Ablk + (size_t)lrow * K + k0 + lcol);
        float4 w4 = *reinterpret_cast<const float4*>(Wblk + (size_t)lrow * K + k0 + lcol);
        As[lcol + 0][lrow] = a4.x; As[lcol + 1][lrow] = a4.y;
        As[lcol + 2][lrow] = a4.z; As[lcol + 3][lrow] = a4.w;
        Ws[lcol + 0][lrow] = w4.x; Ws[lcol + 1][lrow] = w4.y;
        Ws[lcol + 2][lrow] = w4.z; Ws[lcol + 3][lrow] = w4.w;
        __syncthreads();
        #pragma unroll
        for (int k = 0; k < BK; k++) {
            float4 a0 = *reinterpret_cast<const float4*>(&As[k][ty * TM]);
            float4 a1 = *reinterpret_cast<const float4*>(&As[k][ty * TM + 4]);
            float4 w0 = *reinterpret_cast<const float4*>(&Ws[k][tx * TN]);
            float4 w1 = *reinterpret_cast<const float4*>(&Ws[k][tx * TN + 4]);
            float ra[TM] = {a0.x, a0.y, a0.z, a0.w, a1.x, a1.y, a1.z, a1.w};
            float rw[TN] = {w0.x, w0.y, w0.z, w0.w, w1.x, w1.y, w1.z, w1.w};
            #pragma unroll
            for (int i = 0; i < TM; i++)
                #pragma unroll
                for (int j = 0; j < TN; j++)
                    acc[i][j] += ra[i] * rw[j];
        }
        __syncthreads();
    }

    #pragma unroll
    for (int i = 0; i < TM; i++) {
        int m = bm + ty * TM + i;
        #pragma unroll
        for (int j = 0; j < TN; j++) {
            int n = bn + tx * TN + j;
            C[(size_t)m * N + n] = acc[i][j] + bias[n];
        }
    }
}

extern "C" void kernel_launch(void* const* d_in, const int* in_sizes, int n_in,
                              void* d_out, int out_size) {
    const float* x       = (const float*)d_in[0];
    const float* embed_w = (const float*)d_in[1];
    const float* embed_b = (const float*)d_in[2];
    const float* W1      = (const float*)d_in[3];
    const float* b1      = (const float*)d_in[4];
    const float* W2      = (const float*)d_in[5];
    const float* b2      = (const float*)d_in[6];
    const float* ln_g    = (const float*)d_in[7];
    const float* ln_b    = (const float*)d_in[8];
    const float* head_w  = (const float*)d_in[9];
    const float* head_b  = (const float*)d_in[10];
    float* out = (float*)d_out;

    float *p_xemb, *p_hA, *p_hB, *p_u, *p_v0, *p_v1, *p_t, *p_sig;
    float *p_ssum, *p_sss, *p_ctr;
    __half *p_W1h, *p_W2h, *p_hn, *p_hid;
    cudaGetSymbolAddress((void**)&p_xemb, g_xemb);
    cudaGetSymbolAddress((void**)&p_hA, g_hA);
    cudaGetSymbolAddress((void**)&p_hB, g_hB);
    cudaGetSymbolAddress((void**)&p_u, g_u);
    cudaGetSymbolAddress((void**)&p_v0, g_v0);
    cudaGetSymbolAddress((void**)&p_v1, g_v1);
    cudaGetSymbolAddress((void**)&p_t, g_t);
    cudaGetSymbolAddress((void**)&p_sig, g_sig);
    cudaGetSymbolAddress((void**)&p_W1h, g_W1h);
    cudaGetSymbolAddress((void**)&p_W2h, g_W2h);
    cudaGetSymbolAddress((void**)&p_hn, g_hn);
    cudaGetSymbolAddress((void**)&p_hid, g_hid);
    cudaGetSymbolAddress((void**)&p_ssum, g_ssum);
    cudaGetSymbolAddress((void**)&p_sss, g_sss);
    cudaGetSymbolAddress((void**)&p_ctr, g_ctr);

    // scratch aliases (used only before embed / h0 / loop writes)
    float*  p_Vt  = p_xemb;
    float*  p_B   = p_hA;
    __half* p_Vhi = p_hid;
    __half* p_Vlo = p_hid + (size_t)DH * DFF;

    cudaFuncSetAttribute(gemm_tanh,
                         cudaFuncAttributeMaxDynamicSharedMemorySize, GSMEM);
    cudaFuncSetAttribute(gemm_step_ln,
                         cudaFuncAttributeMaxDynamicSharedMemorySize, GSMEM);
    cudaFuncSetAttribute(gram_f16x3,
                         cudaFuncAttributeMaxDynamicSharedMemorySize, G_SMEM);

    // ===== spectral sigma for W1 (v-space: B = W1^T W1) =====
    transpose_kernel<<<dim3(DH / 32, DFF / 32), 256>>>(W1, p_Vt, DFF, DH);
    split_hilo<<<2048, 256>>>(p_Vt, p_Vhi, p_Vlo, (size_t)DH * DFF);
    init_vec_kernel<<<4096, 256>>>(p_B, (size_t)1024 * 1024, 0.f);
    gram_f16x3<<<NSM, 256, G_SMEM>>>(p_Vhi, p_Vlo, p_B, 1024, DFF, 128, 8, 32);
    init_vec_kernel<<<4, 256>>>(p_u, 1024, 0.03125f);
    {
        float* cur = p_u;
        float* oth = p_v0;
        for (int it = 0; it < 15; it++) {
            bmatvec<<<128, 256>>>(p_B, cur, oth, 1024);
            float* tmp = cur; cur = oth; oth = tmp;
        }
        sigma_pq<<<1, 1024>>>(oth, cur, 1024, p_sig);
    }

    // ===== spectral sigma for W2 (u-space: B' = W2 W2^T) =====
    split_hilo<<<2048, 256>>>(W2, p_Vhi, p_Vlo, (size_t)DH * DFF);
    init_vec_kernel<<<4096, 256>>>(p_B, (size_t)1024 * 1024, 0.f);
    gram_f16x3<<<NSM, 256, G_SMEM>>>(p_Vhi, p_Vlo, p_B, 1024, DFF, 128, 8, 32);
    init_vec_kernel<<<16, 256>>>(p_t, 4096, 0.015625f);
    matvec_rows<<<DH, 256>>>(W2, p_t, p_u, DFF);
    {
        float* buf[3] = {p_u, p_v0, p_v1};
        for (int k = 1; k <= 15; k++)
            bmatvec<<<128, 256>>>(p_B, buf[(k - 1) % 3], buf[k % 3], 1024);
        sigma_cab<<<1, 1024>>>(buf[1], buf[2], buf[0], 1024, p_sig + 1);
    }

    // fp16 weights (W / sigma)
    scale_half<<<2048, 256>>>(W1, p_sig, p_W1h, (size_t)DFF * DH);
    scale_half<<<2048, 256>>>(W2, p_sig + 1, p_W2h, (size_t)DH * DFF);

    // x_emb = x @ embed_w^T + embed_b  (fp32 SIMT) -- overwrites Vt scratch
    gemm_f32_bias<<<dim3(DH / BN, B_ / BM), 256>>>(x, embed_w, embed_b, p_xemb, B_, DH, DIN);

    // h0 = x_emb  -- overwrites Gram scratch
    cudaMemcpyAsync(p_hA, p_xemb, (size_t)B_ * DH * sizeof(float), cudaMemcpyDeviceToDevice);

    // zero LN stat accumulators + barrier counter
    init_vec_kernel<<<16, 256>>>(p_ssum, B_, 0.f);
    init_vec_kernel<<<16, 256>>>(p_sss, B_, 0.f);
    init_vec_kernel<<<1, 32>>>(p_ctr, 1, 0.f);

    // hn0 = LN(h0)
    layernorm_half<<<B_, 256>>>(p_hA, ln_g, ln_b, p_hn);

    const int nt1 = (B_ / 256) * (DFF / 128);   // 512 tiles, nx=32
    const int nt2 = (B_ / 256) * (DH / 128);    // 128 tiles, nx=8

    float* hc = p_hA;
    float* hx = p_hB;
    for (int s = 0; s < STEPS; s++) {
        gemm_tanh<<<NSM, 256, GSMEM>>>(
            p_hn, p_W1h, b1, DFF, DH, nt1, DFF / 128, p_hid);
        gemm_step_ln<<<NSM, 256, GSMEM>>>(
            p_hid, p_W2h, b2, DH, DFF, nt2, DH / 128,
            hx, hc, p_xemb, GAMMA_F,
            p_ssum, p_sss, p_ctr, s, ln_g, ln_b, p_hn);
        float* tmp = hc; hc = hx; hx = tmp;
    }

    // out = h @ head_w^T + head_b (fp32 SIMT)
    gemm_f32_bias<<<dim3(DOUT / BN, B_ / BM), 256>>>(hc, head_w, head_b, out, B_, DOUT, DH);
}

// round 15
// speedup vs baseline: 1.0628x; 1.0628x over previous
#include <cuda_runtime.h>
#include <cuda_fp16.h>
#include <math.h>
#include <cstddef>
#include <cstdint>

// ---------------- problem constants ----------------
#define B_    4096
#define DIN   512
#define DH    1024
#define DOUT  256
#define DFF   4096
#define STEPS 30
#define LN_EPSF 1e-5f
#define GAMMA_F 0.17677669529663687f   // 0.5*sqrt(64/512)
#define NSM   148

// ---------------- device scratch (no allocations allowed) ----------------
__device__ float g_xemb[(size_t)B_ * DH];   // also scratch: V^T (16MB) during spectral
__device__ float g_hA[(size_t)B_ * DH];     // also scratch: Gram B (4MB) during spectral
__device__ float g_hB[(size_t)B_ * DH];
__device__ __half g_W1h[(size_t)DFF * DH];
__device__ __half g_W2h[(size_t)DH * DFF];
__device__ __half g_hn[(size_t)B_ * DH];    // also scratch: xh/ewh fp16 before loop
__device__ __half g_hid[(size_t)B_ * DFF];  // also scratch: Vhi/Vlo during spectral
__device__ float g_u[4096];
__device__ float g_v0[4096];
__device__ float g_v1[4096];
__device__ float g_t[4096];
__device__ float g_sig[2];

// ---------------- low-level helpers (plain sm_80+ features only) ----------------
__device__ __forceinline__ uint32_t smem_u32(const void* p) {
    uint32_t a;
    asm("{ .reg .u64 t; cvta.to.shared.u64 t, %1; cvt.u32.u64 %0, t; }" : "=r"(a) : "l"(p));
    return a;
}
__device__ __forceinline__ void cp_async16(uint32_t dst, const void* src) {
    asm volatile("cp.async.cg.shared.global [%0], [%1], 16;" :: "r"(dst), "l"(src) : "memory");
}
__device__ __forceinline__ void cp_commit() {
    asm volatile("cp.async.commit_group;" ::: "memory");
}
template<int N> __device__ __forceinline__ void cp_wait() {
    asm volatile("cp.async.wait_group %0;" :: "n"(N) : "memory");
}
__device__ __forceinline__ void ldm_x4(uint32_t addr, uint32_t* r) {
    asm volatile("ldmatrix.sync.aligned.m8n8.x4.shared.b16 {%0,%1,%2,%3}, [%4];"
        : "=r"(r[0]), "=r"(r[1]), "=r"(r[2]), "=r"(r[3]) : "r"(addr));
}
__device__ __forceinline__ void mma_f16(float* d, const uint32_t* a, const uint32_t* b) {
    asm volatile("mma.sync.aligned.m16n8k16.row.col.f32.f16.f16.f32 "
        "{%0,%1,%2,%3}, {%4,%5,%6,%7}, {%8,%9}, {%0,%1,%2,%3};"
        : "+f"(d[0]), "+f"(d[1]), "+f"(d[2]), "+f"(d[3])
        : "r"(a[0]), "r"(a[1]), "r"(a[2]), "r"(a[3]), "r"(b[0]), "r"(b[1]));
}
__device__ __forceinline__ float tanh_fast(float x) {
    float y;
    asm("tanh.approx.f32 %0, %1;" : "=f"(y) : "f"(x));
    return y;
}
__device__ __forceinline__ uint32_t sw_off(int r, int c) {
    return ((uint32_t)r << 6) + (uint32_t)((c ^ ((r >> 1) & 3)) << 4);
}

// ---------------- small kernels ----------------
__global__ void init_vec_kernel(float* v, size_t n, float val) {
    size_t i = (size_t)blockIdx.x * blockDim.x + threadIdx.x;
    if (i < n) v[i] = val;
}

// out[C][R] = in[R][C]^T, 32x32 tiles, 256 threads
__global__ void transpose_kernel(const float* __restrict__ in, float* __restrict__ out,
                                 int R, int C) {
    __shared__ float tile[32][33];
    int tx = threadIdx.x & 31, ty = threadIdx.x >> 5;
    int bx = blockIdx.x * 32;
    int by = blockIdx.y * 32;
    #pragma unroll
    for (int p = 0; p < 4; p++)
        tile[ty + p * 8][tx] = in[(size_t)(by + ty + p * 8) * C + bx + tx];
    __syncthreads();
    #pragma unroll
    for (int p = 0; p < 4; p++)
        out[(size_t)(bx + ty + p * 8) * R + by + tx] = tile[tx][ty + p * 8];
}

// fp32 -> fp16 hi/lo split (float4 loads)
__global__ void split_hilo(const float* __restrict__ in,
                           __half* __restrict__ hi, __half* __restrict__ lo, size_t n) {
    size_t n4 = n >> 2;
    size_t stride = (size_t)gridDim.x * blockDim.x;
    const float4* in4 = reinterpret_cast<const float4*>(in);
    for (size_t i = (size_t)blockIdx.x * blockDim.x + threadIdx.x; i < n4; i += stride) {
        float4 w = in4[i];
        __half h0 = __float2half_rn(w.x), h1 = __float2half_rn(w.y);
        __half h2 = __float2half_rn(w.z), h3 = __float2half_rn(w.w);
        __half2 a, b, c, d;
        a.x = h0; a.y = h1; b.x = h2; b.y = h3;
        c.x = __float2half_rn(w.x - __half2float(h0));
        c.y = __float2half_rn(w.y - __half2float(h1));
        d.x = __float2half_rn(w.z - __half2float(h2));
        d.y = __float2half_rn(w.w - __half2float(h3));
        *reinterpret_cast<__half2*>(hi + i * 4)     = a;
        *reinterpret_cast<__half2*>(hi + i * 4 + 2) = b;
        *reinterpret_cast<__half2*>(lo + i * 4)     = c;
        *reinterpret_cast<__half2*>(lo + i * 4 + 2) = d;
    }
}

// fp32 -> fp16 (float4 loads)
__global__ void to_half(const float* __restrict__ in, __half* __restrict__ o, size_t n) {
    size_t n4 = n >> 2;
    size_t stride = (size_t)gridDim.x * blockDim.x;
    const float4* in4 = reinterpret_cast<const float4*>(in);
    for (size_t i = (size_t)blockIdx.x * blockDim.x + threadIdx.x; i < n4; i += stride) {
        float4 w = in4[i];
        __half2 a, b;
        a.x = __float2half_rn(w.x); a.y = __float2half_rn(w.y);
        b.x = __float2half_rn(w.z); b.y = __float2half_rn(w.w);
        *reinterpret_cast<__half2*>(o + i * 4)     = a;
        *reinterpret_cast<__half2*>(o + i * 4 + 2) = b;
    }
}

// y[row] = dot(W[row,:], v)
__global__ void matvec_rows(const float* __restrict__ W, const float* __restrict__ v,
                            float* __restrict__ y, int C) {
    int row = blockIdx.x;
    const float4* Wr = reinterpret_cast<const float4*>(W + (size_t)row * C);
    const float4* v4 = reinterpret_cast<const float4*>(v);
    int C4 = C >> 2;
    float acc = 0.f;
    for (int j = threadIdx.x; j < C4; j += 256) {
        float4 a = Wr[j];
        float4 b = v4[j];
        acc += a.x * b.x + a.y * b.y + a.z * b.z + a.w * b.w;
    }
    __shared__ float sm[8];
    #pragma unroll
    for (int o = 16; o > 0; o >>= 1) acc += __shfl_down_sync(0xffffffffu, acc, o);
    if ((threadIdx.x & 31) == 0) sm[threadIdx.x >> 5] = acc;
    __syncthreads();
    if (threadIdx.x < 8) {
        float a = sm[threadIdx.x];
        #pragma unroll
        for (int o = 4; o > 0; o >>= 1) a += __shfl_down_sync(0xffu, a, o);
        if (threadIdx.x == 0) y[row] = a;
    }
}

// y = B @ x, B [n,n] fp32 (L2-resident). 8 rows/block, warp per row.
__global__ void bmatvec(const float* __restrict__ B, const float* __restrict__ x,
                        float* __restrict__ y, int n) {
    int row = blockIdx.x * 8 + (threadIdx.x >> 5);
    int lane = threadIdx.x & 31;
    const float4* Br = reinterpret_cast<const float4*>(B + (size_t)row * n);
    const float4* x4 = reinterpret_cast<const float4*>(x);
    int n4 = n >> 2;
    float acc = 0.f;
    for (int j = lane; j < n4; j += 32) {
        float4 a = Br[j], b = x4[j];
        acc += a.x * b.x + a.y * b.y + a.z * b.z + a.w * b.w;
    }
    #pragma unroll
    for (int o = 16; o > 0; o >>= 1) acc += __shfl_down_sync(0xffffffffu, acc, o);
    if (lane == 0) y[row] = acc;
}

// sigma = sqrt( (q.q) / (p.q) )
__global__ void sigma_pq(const float* __restrict__ p, const float* __restrict__ q,
                         int n, float* __restrict__ sig) {
    float qq = 0.f, pq = 0.f;
    for (int i = threadIdx.x; i < n; i += 1024) {
        float qi = q[i];
        qq += qi * qi;
        pq += p[i] * qi;
    }
    __shared__ float s1[32], s2[32];
    #pragma unroll
    for (int o = 16; o > 0; o >>= 1) {
        qq += __shfl_down_sync(0xffffffffu, qq, o);
        pq += __shfl_down_sync(0xffffffffu, pq, o);
    }
    if ((threadIdx.x & 31) == 0) { s1[threadIdx.x >> 5] = qq; s2[threadIdx.x >> 5] = pq; }
    __syncthreads();
    if (threadIdx.x < 32) {
        float a = s1[threadIdx.x], b = s2[threadIdx.x];
        #pragma unroll
        for (int o = 16; o > 0; o >>= 1) {
            a += __shfl_down_sync(0xffffffffu, a, o);
            b += __shfl_down_sync(0xffffffffu, b, o);
        }
        if (threadIdx.x == 0) sig[0] = sqrtf(a / b);
    }
}

// sigma = sqrt( (a.b) / (c.b) )
__global__ void sigma_cab(const float* __restrict__ c, const float* __restrict__ a,
                          const float* __restrict__ b, int n, float* __restrict__ sig) {
    float ab = 0.f, cb = 0.f;
    for (int i = threadIdx.x; i < n; i += 1024) {
        float bi = b[i];
        ab += a[i] * bi;
        cb += c[i] * bi;
    }
    __shared__ float s1[32], s2[32];
    #pragma unroll
    for (int o = 16; o > 0; o >>= 1) {
        ab += __shfl_down_sync(0xffffffffu, ab, o);
        cb += __shfl_down_sync(0xffffffffu, cb, o);
    }
    if ((threadIdx.x & 31) == 0) { s1[threadIdx.x >> 5] = ab; s2[threadIdx.x >> 5] = cb; }
    __syncthreads();
    if (threadIdx.x < 32) {
        float x = s1[threadIdx.x], y = s2[threadIdx.x];
        #pragma unroll
        for (int o = 16; o > 0; o >>= 1) {
            x += __shfl_down_sync(0xffffffffu, x, o);
            y += __shfl_down_sync(0xffffffffu, y, o);
        }
        if (threadIdx.x == 0) sig[0] = sqrtf(x / y);
    }
}

// Wh = fp16(W / sigma)
__global__ void scale_half(const float* __restrict__ W, const float* __restrict__ sig,
                           __half* __restrict__ Wh, size_t n) {
    float inv = 1.0f / sig[0];
    size_t n4 = n >> 2;
    size_t stride = (size_t)gridDim.x * blockDim.x;
    const float4* W4 = reinterpret_cast<const float4*>(W);
    for (size_t i = (size_t)blockIdx.x * blockDim.x + threadIdx.x; i < n4; i += stride) {
        float4 w = W4[i];
        __half2 a, b;
        a.x = __float2half_rn(w.x * inv); a.y = __float2half_rn(w.y * inv);
        b.x = __float2half_rn(w.z * inv); b.y = __float2half_rn(w.w * inv);
        *reinterpret_cast<__half2*>(Wh + i * 4)     = a;
        *reinterpret_cast<__half2*>(Wh + i * 4 + 2) = b;
    }
}

// ---------------- layernorm: warp-per-row, 8 rows/block, no barriers ----------------
__global__ void layernorm_half(const float* __restrict__ h,
                               const float* __restrict__ g, const float* __restrict__ b,
                               __half* __restrict__ o) {
    int row  = blockIdx.x * 8 + (threadIdx.x >> 5);
    int lane = threadIdx.x & 31;
    const float4* hr = reinterpret_cast<const float4*>(h + (size_t)row * DH);
    float4 xv[8];
    float s = 0.f, ss = 0.f;
    #pragma unroll
    for (int k = 0; k < 8; k++) {
        float4 v = hr[lane + k * 32];
        xv[k] = v;
        s  += v.x + v.y + v.z + v.w;
        ss += v.x * v.x + v.y * v.y + v.z * v.z + v.w * v.w;
    }
    #pragma unroll
    for (int off = 16; off > 0; off >>= 1) {
        s  += __shfl_xor_sync(0xffffffffu, s, off);
        ss += __shfl_xor_sync(0xffffffffu, ss, off);
    }
    float mu  = s * (1.0f / DH);
    float var = ss * (1.0f / DH) - mu * mu;
    float inv = rsqrtf(var + LN_EPSF);
    const float4* g4 = reinterpret_cast<const float4*>(g);
    const float4* b4 = reinterpret_cast<const float4*>(b);
    #pragma unroll
    for (int k = 0; k < 8; k++) {
        int j = lane + k * 32;          // float4 index within row
        float4 gv = g4[j];
        float4 bv = b4[j];
        float4 v = xv[k];
        __half2 o0, o1;
        o0.x = __float2half_rn((v.x - mu) * inv * gv.x + bv.x);
        o0.y = __float2half_rn((v.y - mu) * inv * gv.y + bv.y);
        o1.x = __float2half_rn((v.z - mu) * inv * gv.z + bv.z);
        o1.y = __float2half_rn((v.w - mu) * inv * gv.w + bv.w);
        *reinterpret_cast<__half2*>(o + (size_t)row * DH + j * 4)     = o0;
        *reinterpret_cast<__half2*>(o + (size_t)row * DH + j * 4 + 2) = o1;
    }
}

// ---------------- Gram kernel (spectral): 3-term hi/lo, split-K, atomic accum ----
#define G_MST   4
#define G_ATILE 16384
#define G_WTILE 8192
#define G_STAGE (2 * G_ATILE + 2 * G_WTILE)
#define G_SMEM  (G_MST * G_STAGE)

__device__ __forceinline__ void gram_load_stage(
    uint32_t sbase, int buf, int k0,
    const __half* __restrict__ Vhi, const __half* __restrict__ Vlo,
    int bm, int bn, int K, int tid)
{
    uint32_t base = sbase + (uint32_t)buf * G_STAGE;
    #pragma unroll
    for (int j = 0; j < 8; j++) {
        int c = tid + j * 256;
        int part = c >> 10;
        int rr = (c & 1023) >> 2, c16 = c & 3;
        const __half* g = part ? Vlo : Vhi;
        cp_async16(base + (uint32_t)part * G_ATILE + sw_off(rr, c16),
                   g + (size_t)(bm + rr) * K + k0 + c16 * 8);
    }
    #pragma unroll
    for (int j = 0; j < 4; j++) {
        int c = tid + j * 256;
        int part = c >> 9;
        int rr = (c & 511) >> 2, c16 = c & 3;
        const __half* g = part ? Vlo : Vhi;
        cp_async16(base + 2u * G_ATILE + (uint32_t)part * G_WTILE + sw_off(rr, c16),
                   g + (size_t)(bn + rr) * K + k0 + c16 * 8);
    }
}

__global__ __launch_bounds__(256, 1) void gram_f16x3(
    const __half* __restrict__ Vhi, const __half* __restrict__ Vlo,
    float* __restrict__ G, int N, int K, int nunits, int nx, int kchunks)
{
    extern __shared__ __align__(128) char smem[];
    uint32_t sb = smem_u32(smem);
    int tid = threadIdx.x, wid = tid >> 5, lane = tid & 31;
    int m0 = (wid >> 1) * 64, n0 = (wid & 1) * 64;
    int r16 = lane & 15, kh = lane >> 4;
    int g8 = lane >> 3, l8 = lane & 7;
    int qr = lane >> 2, qc = (lane & 3) * 2;

    for (int unit = blockIdx.x; unit < nunits; unit += gridDim.x) {
        int tile = unit >> 2, kid = unit & 3;
        int bm = (tile / nx) * 256, bn = (tile % nx) * 128;
        int kbase = kid * (kchunks << 5);

        float acc[4][8][4] = {};

        #pragma unroll
        for (int s = 0; s < G_MST - 1; s++) {
            gram_load_stage(sb, s, kbase + (s << 5), Vhi, Vlo, bm, bn, K, tid);
            cp_commit();
        }

        for (int i = 0; i < kchunks; i++) {
            cp_wait<G_MST - 2>();
            __syncthreads();

            uint32_t st = sb + (uint32_t)(i & (G_MST - 1)) * G_STAGE;
            #pragma unroll
            for (int ks = 0; ks < 2; ks++) {
                uint32_t a_hi[4][4], a_lo[4][4], w_hi[4][4], w_lo[4][4];
                #pragma unroll
                for (int mt = 0; mt < 4; mt++) {
                    uint32_t ar = st + sw_off(m0 + mt * 16 + r16, ks * 2 + kh);
                    ldm_x4(ar, a_hi[mt]);
                    ldm_x4(ar + G_ATILE, a_lo[mt]);
                }
                #pragma unroll
                for (int nh = 0; nh < 4; nh++) {
                    uint32_t br = st + 2 * G_ATILE +
                        sw_off(n0 + nh * 16 + (g8 >> 1) * 8 + l8, ks * 2 + (g8 & 1));
                    ldm_x4(br, w_hi[nh]);
                    ldm_x4(br + G_WTILE, w_lo[nh]);
                }
                #pragma unroll
                for (int mt = 0; mt < 4; mt++)
                    #pragma unroll
                    for (int nt = 0; nt < 8; nt++)
                        mma_f16(acc[mt][nt], a_hi[mt], &w_hi[nt >> 1][(nt & 1) * 2]);
                #pragma unroll
                for (int mt = 0; mt < 4; mt++)
                    #pragma unroll
                    for (int nt = 0; nt < 8; nt++)
                        mma_f16(acc[mt][nt], a_hi[mt], &w_lo[nt >> 1][(nt & 1) * 2]);
                #pragma unroll
                for (int mt = 0; mt < 4; mt++)
                    #pragma unroll
                    for (int nt = 0; nt < 8; nt++)
                        mma_f16(acc[mt][nt], a_lo[mt], &w_hi[nt >> 1][(nt & 1) * 2]);
            }

            int nxt = i + G_MST - 1;
            if (nxt < kchunks)
                gram_load_stage(sb, nxt & (G_MST - 1), kbase + (nxt << 5), Vhi, Vlo, bm, bn, K, tid);
            cp_commit();
        }

        #pragma unroll
        for (int mt = 0; mt < 4; mt++) {
            #pragma unroll
            for (int nt = 0; nt < 8; nt++) {
                int c0 = bn + n0 + nt * 8 + qc;
                #pragma unroll
                for (int h = 0; h < 2; h++) {
                    int r = bm + m0 + mt * 16 + qr + h * 8;
                    size_t idx = (size_t)r * N + c0;
                    atomicAdd(&G[idx],     acc[mt][nt][h * 2 + 0]);
                    atomicAdd(&G[idx + 1], acc[mt][nt][h * 2 + 1]);
                }
            }
        }
        __syncthreads();
    }
}

// ---------------- fp16 single-term persistent GEMM ----------------
#define MSTAGES 4
#define ATILEB  (256 * 64)
#define WTILEB  (128 * 64)
#define STAGEB  (ATILEB + WTILEB)
#define GSMEM   (MSTAGES * STAGEB)       // 98304 B

#define EPI_BIAS 0
#define EPI_TANH 1
#define EPI_STEP 2

__device__ __forceinline__ void load_stage(
    uint32_t sbase, int buf, int k0,
    const __half* __restrict__ A, const __half* __restrict__ Wh,
    int bm, int bn, int K, int tid)
{
    uint32_t base = sbase + (uint32_t)buf * STAGEB;
    #pragma unroll
    for (int j = 0; j < 4; j++) {
        int c = tid + j * 256;
        int rr = c >> 2, c16 = c & 3;
        cp_async16(base + sw_off(rr, c16),
                   A + (size_t)(bm + rr) * K + k0 + c16 * 8);
    }
    #pragma unroll
    for (int j = 0; j < 2; j++) {
        int c = tid + j * 256;
        int rr = c >> 2, c16 = c & 3;
        cp_async16(base + (uint32_t)ATILEB + sw_off(rr, c16),
                   Wh + (size_t)(bn + rr) * K + k0 + c16 * 8);
    }
}

template <int EPI>
__global__ __launch_bounds__(256, 1) void gemm_f16(
    const __half* __restrict__ A, const __half* __restrict__ Wh,
    const float* __restrict__ bias, int N, int K, int ntiles, int nx,
    float* __restrict__ Cf, __half* __restrict__ Ch,
    const float* __restrict__ hprev, const float* __restrict__ xemb, float gamma) {

    extern __shared__ __align__(128) char smem[];
    uint32_t sb = smem_u32(smem);
    int tid = threadIdx.x, wid = tid >> 5, lane = tid & 31;
    int m0 = (wid >> 1) * 64, n0 = (wid & 1) * 64;
    int r16 = lane & 15, kh = lane >> 4;
    int g8 = lane >> 3, l8 = lane & 7;
    int qr = lane >> 2, qc = (lane & 3) * 2;
    const int nch = K >> 5;

    for (int tile = blockIdx.x; tile < ntiles; tile += gridDim.x) {
        int bm = (tile / nx) * 256, bn = (tile % nx) * 128;

        float acc[4][8][4] = {};

        #pragma unroll
        for (int s = 0; s < MSTAGES - 1; s++) {
            load_stage(sb, s, s << 5, A, Wh, bm, bn, K, tid);
            cp_commit();
        }

        for (int i = 0; i < nch; i++) {
            cp_wait<MSTAGES - 2>();
            __syncthreads();

            uint32_t st = sb + (uint32_t)(i & (MSTAGES - 1)) * STAGEB;
            #pragma unroll
            for (int ks = 0; ks < 2; ks++) {
                uint32_t a[4][4], w[4][4];
                #pragma unroll
                for (int mt = 0; mt < 4; mt++)
                    ldm_x4(st + sw_off(m0 + mt * 16 + r16, ks * 2 + kh), a[mt]);
                #pragma unroll
                for (int nh = 0; nh < 4; nh++)
                    ldm_x4(st + ATILEB +
                           sw_off(n0 + nh * 16 + (g8 >> 1) * 8 + l8, ks * 2 + (g8 & 1)),
                           w[nh]);
                #pragma unroll
                for (int mt = 0; mt < 4; mt++)
                    #pragma unroll
                    for (int nt = 0; nt < 8; nt++)
                        mma_f16(acc[mt][nt], a[mt], &w[nt >> 1][(nt & 1) * 2]);
            }

            int nxt = i + MSTAGES - 1;
            if (nxt < nch)
                load_stage(sb, nxt & (MSTAGES - 1), nxt << 5, A, Wh, bm, bn, K, tid);
            cp_commit();
        }

        #pragma unroll
        for (int mt = 0; mt < 4; mt++) {
            #pragma unroll
            for (int nt = 0; nt < 8; nt++) {
                int c0 = bn + n0 + nt * 8 + qc;
                float2 bz = *(const float2*)(bias + c0);
                #pragma unroll
                for (int h = 0; h < 2; h++) {
                    int r = bm + m0 + mt * 16 + qr + h * 8;
                    float v0 = acc[mt][nt][h * 2 + 0] + bz.x;
                    float v1 = acc[mt][nt][h * 2 + 1] + bz.y;
                    size_t idx = (size_t)r * N + c0;
                    if (EPI == EPI_TANH) {
                        __half2 hp;
                        hp.x = __float2half_rn(tanh_fast(v0));
                        hp.y = __float2half_rn(tanh_fast(v1));
                        *(__half2*)(Ch + idx) = hp;
                    } else if (EPI == EPI_STEP) {
                        float2 hp = *(const float2*)(hprev + idx);
                        float2 xe = *(const float2*)(xemb + idx);
                        float2 o;
                        o.x = (1.0f - gamma) * hp.x + gamma * (v0 + xe.x);
                        o.y = (1.0f - gamma) * hp.y + gamma * (v1 + xe.y);
                        *(float2*)(Cf + idx) = o;
                    } else {
                        float2 o; o.x = v0; o.y = v1;
                        *(float2*)(Cf + idx) = o;
                    }
                }
            }
        }
        __syncthreads();
    }
}

// ---------------- fp32 SIMT GEMM (head only) ----------------
#define BM 128
#define BN 128
#define BK 8
#define TM 8
#define TN 8

__global__ __launch_bounds__(256, 2) void gemm_f32_bias(
    const float* __restrict__ A, const float* __restrict__ W,
    const float* __restrict__ bias, float* __restrict__ C,
    int M, int N, int K) {

    __shared__ __align__(16) float As[BK][BM];
    __shared__ __align__(16) float Ws[BK][BN];

    int tid = threadIdx.x;
    int bm = blockIdx.y * BM, bn = blockIdx.x * BN;
    const float* Ablk = A + (size_t)bm * K;
    const float* Wblk = W + (size_t)bn * K;

    int lrow = tid >> 1;
    int lcol = (tid & 1) * 4;
    int ty = tid >> 4, tx = tid & 15;

    float acc[TM][TN] = {};

    for (int k0 = 0; k0 < K; k0 += BK) {
        float4 a4 = *reinterpret_cast<const float4*>(Ablk + (size_t)lrow * K + k0 + lcol);
        float4 w4 = *reinterpret_cast<const float4*>(Wblk + (size_t)lrow * K + k0 + lcol);
        As[lcol + 0][lrow] = a4.x; As[lcol + 1][lrow] = a4.y;
        As[lcol + 2][lrow] = a4.z; As[lcol + 3][lrow] = a4.w;
        Ws[lcol + 0][lrow] = w4.x; Ws[lcol + 1][lrow] = w4.y;
        Ws[lcol + 2][lrow] = w4.z; Ws[lcol + 3][lrow] = w4.w;
        __syncthreads();
        #pragma unroll
        for (int k = 0; k < BK; k++) {
            float4 a0 = *reinterpret_cast<const float4*>(&As[k][ty * TM]);
            float4 a1 = *reinterpret_cast<const float4*>(&As[k][ty * TM + 4]);
            float4 w0 = *reinterpret_cast<const float4*>(&Ws[k][tx * TN]);
            float4 w1 = *reinterpret_cast<const float4*>(&Ws[k][tx * TN + 4]);
            float ra[TM] = {a0.x, a0.y, a0.z, a0.w, a1.x, a1.y, a1.z, a1.w};
            float rw[TN] = {w0.x, w0.y, w0.z, w0.w, w1.x, w1.y, w1.z, w1.w};
            #pragma unroll
            for (int i = 0; i < TM; i++)
                #pragma unroll
                for (int j = 0; j < TN; j++)
                    acc[i][j] += ra[i] * rw[j];
        }
        __syncthreads();
    }

    #pragma unroll
    for (int i = 0; i < TM; i++) {
        int m = bm + ty * TM + i;
        #pragma unroll
        for (int j = 0; j < TN; j++) {
            int n = bn + tx * TN + j;
            C[(size_t)m * N + n] = acc[i][j] + bias[n];
        }
    }
}

extern "C" void kernel_launch(void* const* d_in, const int* in_sizes, int n_in,
                              void* d_out, int out_size) {
    const float* x       = (const float*)d_in[0];
    const float* embed_w = (const float*)d_in[1];
    const float* embed_b = (const float*)d_in[2];
    const float* W1      = (const float*)d_in[3];
    const float* b1      = (const float*)d_in[4];
    const float* W2      = (const float*)d_in[5];
    const float* b2      = (const float*)d_in[6];
    const float* ln_g    = (const float*)d_in[7];
    const float* ln_b    = (const float*)d_in[8];
    const float* head_w  = (const float*)d_in[9];
    const float* head_b  = (const float*)d_in[10];
    float* out = (float*)d_out;

    float *p_xemb, *p_hA, *p_hB, *p_u, *p_v0, *p_v1, *p_t, *p_sig;
    __half *p_W1h, *p_W2h, *p_hn, *p_hid;
    cudaGetSymbolAddress((void**)&p_xemb, g_xemb);
    cudaGetSymbolAddress((void**)&p_hA, g_hA);
    cudaGetSymbolAddress((void**)&p_hB, g_hB);
    cudaGetSymbolAddress((void**)&p_u, g_u);
    cudaGetSymbolAddress((void**)&p_v0, g_v0);
    cudaGetSymbolAddress((void**)&p_v1, g_v1);
    cudaGetSymbolAddress((void**)&p_t, g_t);
    cudaGetSymbolAddress((void**)&p_sig, g_sig);
    cudaGetSymbolAddress((void**)&p_W1h, g_W1h);
    cudaGetSymbolAddress((void**)&p_W2h, g_W2h);
    cudaGetSymbolAddress((void**)&p_hn, g_hn);
    cudaGetSymbolAddress((void**)&p_hid, g_hid);

    // scratch aliases
    float*  p_Vt  = p_xemb;                     // 16MB: W1^T (pre-embed)
    float*  p_B   = p_hA;                       // 4MB: Gram matrix (pre-h0)
    __half* p_Vhi = p_hid;                      // 8MB (pre-loop)
    __half* p_Vlo = p_hid + (size_t)DH * DFF;   // 8MB (pre-loop)
    __half* p_xh  = p_hn;                       // 4MB: x fp16 (pre-hn0)
    __half* p_ewh = p_hn + (size_t)B_ * DIN;    // 1MB: embed_w fp16 (pre-hn0)

    cudaFuncSetAttribute(gemm_f16<EPI_BIAS>,
                         cudaFuncAttributeMaxDynamicSharedMemorySize, GSMEM);
    cudaFuncSetAttribute(gemm_f16<EPI_TANH>,
                         cudaFuncAttributeMaxDynamicSharedMemorySize, GSMEM);
    cudaFuncSetAttribute(gemm_f16<EPI_STEP>,
                         cudaFuncAttributeMaxDynamicSharedMemorySize, GSMEM);
    cudaFuncSetAttribute(gram_f16x3,
                         cudaFuncAttributeMaxDynamicSharedMemorySize, G_SMEM);

    // ===== spectral sigma for W1 (v-space: B = W1^T W1) =====
    transpose_kernel<<<dim3(DH / 32, DFF / 32), 256>>>(W1, p_Vt, DFF, DH);
    split_hilo<<<2048, 256>>>(p_Vt, p_Vhi, p_Vlo, (size_t)DH * DFF);
    init_vec_kernel<<<4096, 256>>>(p_B, (size_t)1024 * 1024, 0.f);
    gram_f16x3<<<NSM, 256, G_SMEM>>>(p_Vhi, p_Vlo, p_B, 1024, DFF, 128, 8, 32);
    init_vec_kernel<<<4, 256>>>(p_u, 1024, 0.03125f);
    {
        float* cur = p_u;
        float* oth = p_v0;
        for (int it = 0; it < 15; it++) {
            bmatvec<<<128, 256>>>(p_B, cur, oth, 1024);
            float* tmp = cur; cur = oth; oth = tmp;
        }
        sigma_pq<<<1, 1024>>>(oth, cur, 1024, p_sig);
    }

    // ===== spectral sigma for W2 (u-space: B' = W2 W2^T) =====
    split_hilo<<<2048, 256>>>(W2, p_Vhi, p_Vlo, (size_t)DH * DFF);
    init_vec_kernel<<<4096, 256>>>(p_B, (size_t)1024 * 1024, 0.f);
    gram_f16x3<<<NSM, 256, G_SMEM>>>(p_Vhi, p_Vlo, p_B, 1024, DFF, 128, 8, 32);
    init_vec_kernel<<<16, 256>>>(p_t, 4096, 0.015625f);
    matvec_rows<<<DH, 256>>>(W2, p_t, p_u, DFF);
    {
        float* buf[3] = {p_u, p_v0, p_v1};
        for (int k = 1; k <= 15; k++)
            bmatvec<<<128, 256>>>(p_B, buf[(k - 1) % 3], buf[k % 3], 1024);
        sigma_cab<<<1, 1024>>>(buf[1], buf[2], buf[0], 1024, p_sig + 1);
    }

    // fp16 weights (W / sigma)
    scale_half<<<2048, 256>>>(W1, p_sig, p_W1h, (size_t)DFF * DH);
    scale_half<<<2048, 256>>>(W2, p_sig + 1, p_W2h, (size_t)DH * DFF);

    // x_emb = x @ embed_w^T + embed_b  via fp16 tensor path
    to_half<<<1024, 256>>>(x, p_xh, (size_t)B_ * DIN);
    to_half<<<256, 256>>>(embed_w, p_ewh, (size_t)DH * DIN);
    gemm_f16<EPI_BIAS><<<NSM, 256, GSMEM>>>(
        p_xh, p_ewh, embed_b, DH, DIN, (B_ / 256) * (DH / 128), DH / 128,
        p_xemb, nullptr, nullptr, nullptr, 0.f);

    // h0 = x_emb  -- overwrites Gram scratch
    cudaMemcpyAsync(p_hA, p_xemb, (size_t)B_ * DH * sizeof(float), cudaMemcpyDeviceToDevice);

    // hn0 = LN(h0) -- overwrites xh/ewh scratch
    layernorm_half<<<B_ / 8, 256>>>(p_hA, ln_g, ln_b, p_hn);

    const int nt1 = (B_ / 256) * (DFF / 128);   // 512 tiles, nx=32
    const int nt2 = (B_ / 256) * (DH / 128);    // 128 tiles, nx=8

    float* hc = p_hA;
    float* hx = p_hB;
    for (int s = 0; s < STEPS; s++) {
        gemm_f16<EPI_TANH><<<NSM, 256, GSMEM>>>(
            p_hn, p_W1h, b1, DFF, DH, nt1, DFF / 128,
            nullptr, p_hid, nullptr, nullptr, 0.f);
        gemm_f16<EPI_STEP><<<NSM, 256, GSMEM>>>(
            p_hid, p_W2h, b2, DH, DFF, nt2, DH / 128,
            hx, nullptr, hc, p_xemb, GAMMA_F);
        float* tmp = hc; hc = hx; hx = tmp;
        if (s + 1 < STEPS)
            layernorm_half<<<B_ / 8, 256>>>(hc, ln_g, ln_b, p_hn);
    }

    // out = h @ head_w^T + head_b (fp32 SIMT)
    gemm_f32_bias<<<dim3(DOUT / BN, B_ / BM), 256>>>(hc, head_w, head_b, out, B_, DOUT, DH);
}

// round 16
// speedup vs baseline: 1.0946x; 1.0299x over previous
#include <cuda_runtime.h>
#include <cuda_fp16.h>
#include <math.h>
#include <cstddef>
#include <cstdint>

// ---------------- problem constants ----------------
#define B_    4096
#define DIN   512
#define DH    1024
#define DOUT  256
#define DFF   4096
#define STEPS 30
#define LN_EPSF 1e-5f
#define GAMMA_F 0.17677669529663687f   // 0.5*sqrt(64/512)
#define NSM   148
#define PI_NB 128                       // power_iter grid (co-resident)

// ---------------- device scratch (no allocations allowed) ----------------
__device__ float g_xemb[(size_t)B_ * DH];   // h0 (and x_emb) — written once pre-loop
__device__ float g_hA[(size_t)B_ * DH];     // also scratch: Gram B (4MB) during spectral
__device__ float g_hB[(size_t)B_ * DH];
__device__ __half g_W1h[(size_t)DFF * DH];
__device__ __half g_W2h[(size_t)DH * DFF];
__device__ __half g_hn[(size_t)B_ * DH];    // also scratch: xh/ewh fp16 before loop
__device__ __half g_hid[(size_t)B_ * DFF];  // also scratch: Vhi/Vlo during spectral; h-fp16 at end
__device__ float g_u[4096];
__device__ float g_v0[4096];
__device__ float g_v1[4096];
__device__ float g_t[4096];
__device__ float g_sig[2];
__device__ int   g_ictr[1];

// ---------------- low-level helpers (plain sm_80+ features only) ----------------
__device__ __forceinline__ uint32_t smem_u32(const void* p) {
    uint32_t a;
    asm("{ .reg .u64 t; cvta.to.shared.u64 t, %1; cvt.u32.u64 %0, t; }" : "=r"(a) : "l"(p));
    return a;
}
__device__ __forceinline__ void cp_async16(uint32_t dst, const void* src) {
    asm volatile("cp.async.cg.shared.global [%0], [%1], 16;" :: "r"(dst), "l"(src) : "memory");
}
__device__ __forceinline__ void cp_commit() {
    asm volatile("cp.async.commit_group;" ::: "memory");
}
template<int N> __device__ __forceinline__ void cp_wait() {
    asm volatile("cp.async.wait_group %0;" :: "n"(N) : "memory");
}
__device__ __forceinline__ void ldm_x4(uint32_t addr, uint32_t* r) {
    asm volatile("ldmatrix.sync.aligned.m8n8.x4.shared.b16 {%0,%1,%2,%3}, [%4];"
        : "=r"(r[0]), "=r"(r[1]), "=r"(r[2]), "=r"(r[3]) : "r"(addr));
}
__device__ __forceinline__ void mma_f16(float* d, const uint32_t* a, const uint32_t* b) {
    asm volatile("mma.sync.aligned.m16n8k16.row.col.f32.f16.f16.f32 "
        "{%0,%1,%2,%3}, {%4,%5,%6,%7}, {%8,%9}, {%0,%1,%2,%3};"
        : "+f"(d[0]), "+f"(d[1]), "+f"(d[2]), "+f"(d[3])
        : "r"(a[0]), "r"(a[1]), "r"(a[2]), "r"(a[3]), "r"(b[0]), "r"(b[1]));
}
__device__ __forceinline__ float tanh_fast(float x) {
    float y;
    asm("tanh.approx.f32 %0, %1;" : "=f"(y) : "f"(x));
    return y;
}
__device__ __forceinline__ uint32_t sw_off(int r, int c) {
    return ((uint32_t)r << 6) + (uint32_t)((c ^ ((r >> 1) & 3)) << 4);
}

// ---------------- small kernels ----------------
__global__ void init_vec_kernel(float* v, size_t n, float val) {
    size_t i = (size_t)blockIdx.x * blockDim.x + threadIdx.x;
    if (i < n) v[i] = val;
}

// out[C][R] = in[R][C]^T split into fp16 hi/lo directly
__global__ void transpose_split(const float* __restrict__ in,
                                __half* __restrict__ hi, __half* __restrict__ lo,
                                int R, int C) {
    __shared__ float tile[32][33];
    int tx = threadIdx.x & 31, ty = threadIdx.x >> 5;
    int bx = blockIdx.x * 32;
    int by = blockIdx.y * 32;
    #pragma unroll
    for (int p = 0; p < 4; p++)
        tile[ty + p * 8][tx] = in[(size_t)(by + ty + p * 8) * C + bx + tx];
    __syncthreads();
    #pragma unroll
    for (int p = 0; p < 4; p++) {
        float v = tile[tx][ty + p * 8];
        __half h = __float2half_rn(v);
        size_t oidx = (size_t)(bx + ty + p * 8) * R + by + tx;
        hi[oidx] = h;
        lo[oidx] = __float2half_rn(v - __half2float(h));
    }
}

// fp32 -> fp16 hi/lo split (float4 loads)
__global__ void split_hilo(const float* __restrict__ in,
                           __half* __restrict__ hi, __half* __restrict__ lo, size_t n) {
    size_t n4 = n >> 2;
    size_t stride = (size_t)gridDim.x * blockDim.x;
    const float4* in4 = reinterpret_cast<const float4*>(in);
    for (size_t i = (size_t)blockIdx.x * blockDim.x + threadIdx.x; i < n4; i += stride) {
        float4 w = in4[i];
        __half h0 = __float2half_rn(w.x), h1 = __float2half_rn(w.y);
        __half h2 = __float2half_rn(w.z), h3 = __float2half_rn(w.w);
        __half2 a, b, c, d;
        a.x = h0; a.y = h1; b.x = h2; b.y = h3;
        c.x = __float2half_rn(w.x - __half2float(h0));
        c.y = __float2half_rn(w.y - __half2float(h1));
        d.x = __float2half_rn(w.z - __half2float(h2));
        d.y = __float2half_rn(w.w - __half2float(h3));
        *reinterpret_cast<__half2*>(hi + i * 4)     = a;
        *reinterpret_cast<__half2*>(hi + i * 4 + 2) = b;
        *reinterpret_cast<__half2*>(lo + i * 4)     = c;
        *reinterpret_cast<__half2*>(lo + i * 4 + 2) = d;
    }
}

// fp32 -> fp16 (float4 loads)
__global__ void to_half(const float* __restrict__ in, __half* __restrict__ o, size_t n) {
    size_t n4 = n >> 2;
    size_t stride = (size_t)gridDim.x * blockDim.x;
    const float4* in4 = reinterpret_cast<const float4*>(in);
    for (size_t i = (size_t)blockIdx.x * blockDim.x + threadIdx.x; i < n4; i += stride) {
        float4 w = in4[i];
        __half2 a, b;
        a.x = __float2half_rn(w.x); a.y = __float2half_rn(w.y);
        b.x = __float2half_rn(w.z); b.y = __float2half_rn(w.w);
        *reinterpret_cast<__half2*>(o + i * 4)     = a;
        *reinterpret_cast<__half2*>(o + i * 4 + 2) = b;
    }
}

// y[row] = dot(W[row,:], v)
__global__ void matvec_rows(const float* __restrict__ W, const float* __restrict__ v,
                            float* __restrict__ y, int C) {
    int row = blockIdx.x;
    const float4* Wr = reinterpret_cast<const float4*>(W + (size_t)row * C);
    const float4* v4 = reinterpret_cast<const float4*>(v);
    int C4 = C >> 2;
    float acc = 0.f;
    for (int j = threadIdx.x; j < C4; j += 256) {
        float4 a = Wr[j];
        float4 b = v4[j];
        acc += a.x * b.x + a.y * b.y + a.z * b.z + a.w * b.w;
    }
    __shared__ float sm[8];
    #pragma unroll
    for (int o = 16; o > 0; o >>= 1) acc += __shfl_down_sync(0xffffffffu, acc, o);
    if ((threadIdx.x & 31) == 0) sm[threadIdx.x >> 5] = acc;
    __syncthreads();
    if (threadIdx.x < 8) {
        float a = sm[threadIdx.x];
        #pragma unroll
        for (int o = 4; o > 0; o >>= 1) a += __shfl_down_sync(0xffu, a, o);
        if (threadIdx.x == 0) y[row] = a;
    }
}

// monotone grid barrier (ctr zeroed by a preceding init node each replay)
__device__ __forceinline__ void grid_bar(int* ctr, int gen, int nb) {
    __threadfence();
    __syncthreads();
    if (threadIdx.x == 0) {
        atomicAdd(ctr, 1);
        while (atomicAdd(ctr, 0) < gen * nb) { }
    }
    __syncthreads();
}

// One-launch power iteration: 15x (y = B @ x) + sigma.
// 128 blocks x 256 thr; 8 warps/block => 1024 rows total (warp per row).
// mode 0: sig = sqrt((x_k.x_k)/(x_{k-1}.x_k));  mode 1: sig = sqrt((x_{k-1}.x_k)/(x_{k-2}.x_k))
__global__ __launch_bounds__(256, 1) void power_iter(
    const float* __restrict__ B,
    float* b0, float* b1, float* b2,
    int n, int iters, int* ctr, int mode, float initval, float* sig) {

    float* buf[3] = {b0, b1, b2};
    int nb = gridDim.x;
    int warp = threadIdx.x >> 5, lane = threadIdx.x & 31;
    int row = blockIdx.x * 8 + warp;
    int gen = 0;

    if (initval != 0.f) {
        for (int i = blockIdx.x * blockDim.x + threadIdx.x; i < n; i += nb * blockDim.x)
            b0[i] = initval;
        gen++;
        grid_bar(ctr, gen, nb);
    }

    for (int k = 0; k < iters; k++) {
        const float* xc = buf[k % 3];
        float* yc = buf[(k + 1) % 3];
        const float4* Br = reinterpret_cast<const float4*>(B + (size_t)row * n);
        const float4* x4 = reinterpret_cast<const float4*>(xc);
        float acc = 0.f;
        for (int j = lane; j < (n >> 2); j += 32) {
            float4 a = Br[j], b = x4[j];
            acc += a.x * b.x + a.y * b.y + a.z * b.z + a.w * b.w;
        }
        #pragma unroll
        for (int o = 16; o > 0; o >>= 1) acc += __shfl_xor_sync(0xffffffffu, acc, o);
        if (lane == 0) yc[row] = acc;
        gen++;
        grid_bar(ctr, gen, nb);
    }

    if (blockIdx.x == 0) {
        const float* vb = buf[iters % 3];          // x_k
        const float* va = buf[(iters + 2) % 3];    // x_{k-1}
        const float* vc = buf[(iters + 1) % 3];    // x_{k-2}
        float d1 = 0.f, d2 = 0.f;
        for (int i = threadIdx.x; i < n; i += blockDim.x) {
            float bi = vb[i];
            if (mode == 0) { d1 += bi * bi;     d2 += va[i] * bi; }
            else           { d1 += va[i] * bi;  d2 += vc[i] * bi; }
        }
        __shared__ float s1[8], s2[8];
        #pragma unroll
        for (int o = 16; o > 0; o >>= 1) {
            d1 += __shfl_xor_sync(0xffffffffu, d1, o);
            d2 += __shfl_xor_sync(0xffffffffu, d2, o);
        }
        if (lane == 0) { s1[warp] = d1; s2[warp] = d2; }
        __syncthreads();
        if (threadIdx.x < 8) {
            d1 = s1[threadIdx.x]; d2 = s2[threadIdx.x];
            #pragma unroll
            for (int o = 4; o > 0; o >>= 1) {
                d1 += __shfl_xor_sync(0xffu, d1, o);
                d2 += __shfl_xor_sync(0xffu, d2, o);
            }
            if (threadIdx.x == 0) sig[0] = sqrtf(d1 / d2);
        }
    }
}

// Wh = fp16(W / sigma)
__global__ void scale_half(const float* __restrict__ W, const float* __restrict__ sig,
                           __half* __restrict__ Wh, size_t n) {
    float inv = 1.0f / sig[0];
    size_t n4 = n >> 2;
    size_t stride = (size_t)gridDim.x * blockDim.x;
    const float4* W4 = reinterpret_cast<const float4*>(W);
    for (size_t i = (size_t)blockIdx.x * blockDim.x + threadIdx.x; i < n4; i += stride) {
        float4 w = W4[i];
        __half2 a, b;
        a.x = __float2half_rn(w.x * inv); a.y = __float2half_rn(w.y * inv);
        b.x = __float2half_rn(w.z * inv); b.y = __float2half_rn(w.w * inv);
        *reinterpret_cast<__half2*>(Wh + i * 4)     = a;
        *reinterpret_cast<__half2*>(Wh + i * 4 + 2) = b;
    }
}

// ---------------- layernorm: warp-per-row, 8 rows/block, no barriers ----------------
__global__ void layernorm_half(const float* __restrict__ h,
                               const float* __restrict__ g, const float* __restrict__ b,
                               __half* __restrict__ o) {
    int row  = blockIdx.x * 8 + (threadIdx.x >> 5);
    int lane = threadIdx.x & 31;
    const float4* hr = reinterpret_cast<const float4*>(h + (size_t)row * DH);
    float4 xv[8];
    float s = 0.f, ss = 0.f;
    #pragma unroll
    for (int k = 0; k < 8; k++) {
        float4 v = hr[lane + k * 32];
        xv[k] = v;
        s  += v.x + v.y + v.z + v.w;
        ss += v.x * v.x + v.y * v.y + v.z * v.z + v.w * v.w;
    }
    #pragma unroll
    for (int off = 16; off > 0; off >>= 1) {
        s  += __shfl_xor_sync(0xffffffffu, s, off);
        ss += __shfl_xor_sync(0xffffffffu, ss, off);
    }
    float mu  = s * (1.0f / DH);
    float var = ss * (1.0f / DH) - mu * mu;
    float inv = rsqrtf(var + LN_EPSF);
    const float4* g4 = reinterpret_cast<const float4*>(g);
    const float4* b4 = reinterpret_cast<const float4*>(b);
    #pragma unroll
    for (int k = 0; k < 8; k++) {
        int j = lane + k * 32;
        float4 gv = g4[j];
        float4 bv = b4[j];
        float4 v = xv[k];
        __half2 o0, o1;
        o0.x = __float2half_rn((v.x - mu) * inv * gv.x + bv.x);
        o0.y = __float2half_rn((v.y - mu) * inv * gv.y + bv.y);
        o1.x = __float2half_rn((v.z - mu) * inv * gv.z + bv.z);
        o1.y = __float2half_rn((v.w - mu) * inv * gv.w + bv.w);
        *reinterpret_cast<__half2*>(o + (size_t)row * DH + j * 4)     = o0;
        *reinterpret_cast<__half2*>(o + (size_t)row * DH + j * 4 + 2) = o1;
    }
}

// ---------------- Gram kernel (spectral): 3-term hi/lo, split-K, atomic accum ----
#define G_MST   4
#define G_ATILE 16384
#define G_WTILE 8192
#define G_STAGE (2 * G_ATILE + 2 * G_WTILE)
#define G_SMEM  (G_MST * G_STAGE)

__device__ __forceinline__ void gram_load_stage(
    uint32_t sbase, int buf, int k0,
    const __half* __restrict__ Vhi, const __half* __restrict__ Vlo,
    int bm, int bn, int K, int tid)
{
    uint32_t base = sbase + (uint32_t)buf * G_STAGE;
    #pragma unroll
    for (int j = 0; j < 8; j++) {
        int c = tid + j * 256;
        int part = c >> 10;
        int rr = (c & 1023) >> 2, c16 = c & 3;
        const __half* g = part ? Vlo : Vhi;
        cp_async16(base + (uint32_t)part * G_ATILE + sw_off(rr, c16),
                   g + (size_t)(bm + rr) * K + k0 + c16 * 8);
    }
    #pragma unroll
    for (int j = 0; j < 4; j++) {
        int c = tid + j * 256;
        int part = c >> 9;
        int rr = (c & 511) >> 2, c16 = c & 3;
        const __half* g = part ? Vlo : Vhi;
        cp_async16(base + 2u * G_ATILE + (uint32_t)part * G_WTILE + sw_off(rr, c16),
                   g + (size_t)(bn + rr) * K + k0 + c16 * 8);
    }
}

__global__ __launch_bounds__(256, 1) void gram_f16x3(
    const __half* __restrict__ Vhi, const __half* __restrict__ Vlo,
    float* __restrict__ G, int N, int K, int nunits, int nx, int kchunks)
{
    extern __shared__ __align__(128) char smem[];
    uint32_t sb = smem_u32(smem);
    int tid = threadIdx.x, wid = tid >> 5, lane = tid & 31;
    int m0 = (wid >> 1) * 64, n0 = (wid & 1) * 64;
    int r16 = lane & 15, kh = lane >> 4;
    int g8 = lane >> 3, l8 = lane & 7;
    int qr = lane >> 2, qc = (lane & 3) * 2;

    for (int unit = blockIdx.x; unit < nunits; unit += gridDim.x) {
        int tile = unit >> 2, kid = unit & 3;
        int bm = (tile / nx) * 256, bn = (tile % nx) * 128;
        int kbase = kid * (kchunks << 5);

        float acc[4][8][4] = {};

        #pragma unroll
        for (int s = 0; s < G_MST - 1; s++) {
            gram_load_stage(sb, s, kbase + (s << 5), Vhi, Vlo, bm, bn, K, tid);
            cp_commit();
        }

        for (int i = 0; i < kchunks; i++) {
            cp_wait<G_MST - 2>();
            __syncthreads();

            uint32_t st = sb + (uint32_t)(i & (G_MST - 1)) * G_STAGE;
            #pragma unroll
            for (int ks = 0; ks < 2; ks++) {
                uint32_t a_hi[4][4], a_lo[4][4], w_hi[4][4], w_lo[4][4];
                #pragma unroll
                for (int mt = 0; mt < 4; mt++) {
                    uint32_t ar = st + sw_off(m0 + mt * 16 + r16, ks * 2 + kh);
                    ldm_x4(ar, a_hi[mt]);
                    ldm_x4(ar + G_ATILE, a_lo[mt]);
                }
                #pragma unroll
                for (int nh = 0; nh < 4; nh++) {
                    uint32_t br = st + 2 * G_ATILE +
                        sw_off(n0 + nh * 16 + (g8 >> 1) * 8 + l8, ks * 2 + (g8 & 1));
                    ldm_x4(br, w_hi[nh]);
                    ldm_x4(br + G_WTILE, w_lo[nh]);
                }
                #pragma unroll
                for (int mt = 0; mt < 4; mt++)
                    #pragma unroll
                    for (int nt = 0; nt < 8; nt++)
                        mma_f16(acc[mt][nt], a_hi[mt], &w_hi[nt >> 1][(nt & 1) * 2]);
                #pragma unroll
                for (int mt = 0; mt < 4; mt++)
                    #pragma unroll
                    for (int nt = 0; nt < 8; nt++)
                        mma_f16(acc[mt][nt], a_hi[mt], &w_lo[nt >> 1][(nt & 1) * 2]);
                #pragma unroll
                for (int mt = 0; mt < 4; mt++)
                    #pragma unroll
                    for (int nt = 0; nt < 8; nt++)
                        mma_f16(acc[mt][nt], a_lo[mt], &w_hi[nt >> 1][(nt & 1) * 2]);
            }

            int nxt = i + G_MST - 1;
            if (nxt < kchunks)
                gram_load_stage(sb, nxt & (G_MST - 1), kbase + (nxt << 5), Vhi, Vlo, bm, bn, K, tid);
            cp_commit();
        }

        #pragma unroll
        for (int mt = 0; mt < 4; mt++) {
            #pragma unroll
            for (int nt = 0; nt < 8; nt++) {
                int c0 = bn + n0 + nt * 8 + qc;
                #pragma unroll
                for (int h = 0; h < 2; h++) {
                    int r = bm + m0 + mt * 16 + qr + h * 8;
                    size_t idx = (size_t)r * N + c0;
                    atomicAdd(&G[idx],     acc[mt][nt][h * 2 + 0]);
                    atomicAdd(&G[idx + 1], acc[mt][nt][h * 2 + 1]);
                }
            }
        }
        __syncthreads();
    }
}

// ---------------- fp16 single-term persistent GEMM ----------------
#define MSTAGES 4
#define ATILEB  (256 * 64)
#define WTILEB  (128 * 64)
#define STAGEB  (ATILEB + WTILEB)
#define GSMEM   (MSTAGES * STAGEB)       // 98304 B

#define EPI_BIAS 0
#define EPI_TANH 1
#define EPI_STEP 2

__device__ __forceinline__ void load_stage(
    uint32_t sbase, int buf, int k0,
    const __half* __restrict__ A, const __half* __restrict__ Wh,
    int bm, int bn, int K, int tid)
{
    uint32_t base = sbase + (uint32_t)buf * STAGEB;
    #pragma unroll
    for (int j = 0; j < 4; j++) {
        int c = tid + j * 256;
        int rr = c >> 2, c16 = c & 3;
        cp_async16(base + sw_off(rr, c16),
                   A + (size_t)(bm + rr) * K + k0 + c16 * 8);
    }
    #pragma unroll
    for (int j = 0; j < 2; j++) {
        int c = tid + j * 256;
        int rr = c >> 2, c16 = c & 3;
        cp_async16(base + (uint32_t)ATILEB + sw_off(rr, c16),
                   Wh + (size_t)(bn + rr) * K + k0 + c16 * 8);
    }
}

template <int EPI>
__global__ __launch_bounds__(256, 1) void gemm_f16(
    const __half* __restrict__ A, const __half* __restrict__ Wh,
    const float* __restrict__ bias, int N, int K, int ntiles, int nx,
    float* __restrict__ Cf, __half* __restrict__ Ch,
    const float* __restrict__ hprev, const float* __restrict__ xemb, float gamma) {

    extern __shared__ __align__(128) char smem[];
    uint32_t sb = smem_u32(smem);
    int tid = threadIdx.x, wid = tid >> 5, lane = tid & 31;
    int m0 = (wid >> 1) * 64, n0 = (wid & 1) * 64;
    int r16 = lane & 15, kh = lane >> 4;
    int g8 = lane >> 3, l8 = lane & 7;
    int qr = lane >> 2, qc = (lane & 3) * 2;
    const int nch = K >> 5;

    for (int tile = blockIdx.x; tile < ntiles; tile += gridDim.x) {
        int bm = (tile / nx) * 256, bn = (tile % nx) * 128;

        float acc[4][8][4] = {};

        #pragma unroll
        for (int s = 0; s < MSTAGES - 1; s++) {
            load_stage(sb, s, s << 5, A, Wh, bm, bn, K, tid);
            cp_commit();
        }

        for (int i = 0; i < nch; i++) {
            cp_wait<MSTAGES - 2>();
            __syncthreads();

            uint32_t st = sb + (uint32_t)(i & (MSTAGES - 1)) * STAGEB;
            #pragma unroll
            for (int ks = 0; ks < 2; ks++) {
                uint32_t a[4][4], w[4][4];
                #pragma unroll
                for (int mt = 0; mt < 4; mt++)
                    ldm_x4(st + sw_off(m0 + mt * 16 + r16, ks * 2 + kh), a[mt]);
                #pragma unroll
                for (int nh = 0; nh < 4; nh++)
                    ldm_x4(st + ATILEB +
                           sw_off(n0 + nh * 16 + (g8 >> 1) * 8 + l8, ks * 2 + (g8 & 1)),
                           w[nh]);
                #pragma unroll
                for (int mt = 0; mt < 4; mt++)
                    #pragma unroll
                    for (int nt = 0; nt < 8; nt++)
                        mma_f16(acc[mt][nt], a[mt], &w[nt >> 1][(nt & 1) * 2]);
            }

            int nxt = i + MSTAGES - 1;
            if (nxt < nch)
                load_stage(sb, nxt & (MSTAGES - 1), nxt << 5, A, Wh, bm, bn, K, tid);
            cp_commit();
        }

        #pragma unroll
        for (int mt = 0; mt < 4; mt++) {
            #pragma unroll
            for (int nt = 0; nt < 8; nt++) {
                int c0 = bn + n0 + nt * 8 + qc;
                float2 bz = *(const float2*)(bias + c0);
                #pragma unroll
                for (int h = 0; h < 2; h++) {
                    int r = bm + m0 + mt * 16 + qr + h * 8;
                    float v0 = acc[mt][nt][h * 2 + 0] + bz.x;
                    float v1 = acc[mt][nt][h * 2 + 1] + bz.y;
                    size_t idx = (size_t)r * N + c0;
                    if (EPI == EPI_TANH) {
                        __half2 hp;
                        hp.x = __float2half_rn(tanh_fast(v0));
                        hp.y = __float2half_rn(tanh_fast(v1));
                        *(__half2*)(Ch + idx) = hp;
                    } else if (EPI == EPI_STEP) {
                        float2 hp = *(const float2*)(hprev + idx);
                        float2 xe = *(const float2*)(xemb + idx);
                        float2 o;
                        o.x = (1.0f - gamma) * hp.x + gamma * (v0 + xe.x);
                        o.y = (1.0f - gamma) * hp.y + gamma * (v1 + xe.y);
                        *(float2*)(Cf + idx) = o;
                    } else {
                        float2 o; o.x = v0; o.y = v1;
                        *(float2*)(Cf + idx) = o;
                    }
                }
            }
        }
        __syncthreads();
    }
}

extern "C" void kernel_launch(void* const* d_in, const int* in_sizes, int n_in,
                              void* d_out, int out_size) {
    const float* x       = (const float*)d_in[0];
    const float* embed_w = (const float*)d_in[1];
    const float* embed_b = (const float*)d_in[2];
    const float* W1      = (const float*)d_in[3];
    const float* b1      = (const float*)d_in[4];
    const float* W2      = (const float*)d_in[5];
    const float* b2      = (const float*)d_in[6];
    const float* ln_g    = (const float*)d_in[7];
    const float* ln_b    = (const float*)d_in[8];
    const float* head_w  = (const float*)d_in[9];
    const float* head_b  = (const float*)d_in[10];
    float* out = (float*)d_out;

    float *p_xemb, *p_hA, *p_hB, *p_u, *p_v0, *p_v1, *p_t, *p_sig;
    int* p_ictr;
    __half *p_W1h, *p_W2h, *p_hn, *p_hid;
    cudaGetSymbolAddress((void**)&p_xemb, g_xemb);
    cudaGetSymbolAddress((void**)&p_hA, g_hA);
    cudaGetSymbolAddress((void**)&p_hB, g_hB);
    cudaGetSymbolAddress((void**)&p_u, g_u);
    cudaGetSymbolAddress((void**)&p_v0, g_v0);
    cudaGetSymbolAddress((void**)&p_v1, g_v1);
    cudaGetSymbolAddress((void**)&p_t, g_t);
    cudaGetSymbolAddress((void**)&p_sig, g_sig);
    cudaGetSymbolAddress((void**)&p_ictr, g_ictr);
    cudaGetSymbolAddress((void**)&p_W1h, g_W1h);
    cudaGetSymbolAddress((void**)&p_W2h, g_W2h);
    cudaGetSymbolAddress((void**)&p_hn, g_hn);
    cudaGetSymbolAddress((void**)&p_hid, g_hid);

    // scratch aliases
    float*  p_B   = p_hA;                        // 4MB Gram (pre-loop)
    __half* p_Vhi = p_hid;                       // 8MB (pre-loop)
    __half* p_Vlo = p_hid + (size_t)DH * DFF;    // 8MB (pre-loop)
    __half* p_xh  = p_hn;                        // 4MB x fp16 (pre-hn0)
    __half* p_ewh = p_hn + (size_t)B_ * DIN;     // 1MB embed_w fp16 (pre-hn0)
    __half* p_hf  = p_hid;                       // 8MB h-final fp16 (post-loop)
    __half* p_hwh = p_hid + (size_t)B_ * DH;     // head_w fp16 (post-loop area, but fill early is unsafe; fill post-loop)

    cudaFuncSetAttribute(gemm_f16<EPI_BIAS>,
                         cudaFuncAttributeMaxDynamicSharedMemorySize, GSMEM);
    cudaFuncSetAttribute(gemm_f16<EPI_TANH>,
                         cudaFuncAttributeMaxDynamicSharedMemorySize, GSMEM);
    cudaFuncSetAttribute(gemm_f16<EPI_STEP>,
                         cudaFuncAttributeMaxDynamicSharedMemorySize, GSMEM);
    cudaFuncSetAttribute(gram_f16x3,
                         cudaFuncAttributeMaxDynamicSharedMemorySize, G_SMEM);

    // ===== spectral sigma for W1 (v-space: B = W1^T W1) =====
    transpose_split<<<dim3(DH / 32, DFF / 32), 256>>>(W1, p_Vhi, p_Vlo, DFF, DH);
    init_vec_kernel<<<4096, 256>>>(p_B, (size_t)1024 * 1024, 0.f);
    gram_f16x3<<<NSM, 256, G_SMEM>>>(p_Vhi, p_Vlo, p_B, 1024, DFF, 128, 8, 32);
    init_vec_kernel<<<1, 32>>>((float*)p_ictr, 1, 0.f);
    power_iter<<<PI_NB, 256>>>(p_B, p_u, p_v0, p_v1, 1024, 15, p_ictr, 0, 0.03125f, p_sig);

    // ===== spectral sigma for W2 (u-space: B' = W2 W2^T) =====
    split_hilo<<<2048, 256>>>(W2, p_Vhi, p_Vlo, (size_t)DH * DFF);
    init_vec_kernel<<<4096, 256>>>(p_B, (size_t)1024 * 1024, 0.f);
    gram_f16x3<<<NSM, 256, G_SMEM>>>(p_Vhi, p_Vlo, p_B, 1024, DFF, 128, 8, 32);
    init_vec_kernel<<<16, 256>>>(p_t, 4096, 0.015625f);
    matvec_rows<<<DH, 256>>>(W2, p_t, p_u, DFF);    // x0 = W2 v0
    init_vec_kernel<<<1, 32>>>((float*)p_ictr, 1, 0.f);
    power_iter<<<PI_NB, 256>>>(p_B, p_u, p_v0, p_v1, 1024, 15, p_ictr, 1, 0.f, p_sig + 1);

    // fp16 weights (W / sigma)
    scale_half<<<2048, 256>>>(W1, p_sig, p_W1h, (size_t)DFF * DH);
    scale_half<<<2048, 256>>>(W2, p_sig + 1, p_W2h, (size_t)DH * DFF);

    // x_emb = x @ embed_w^T + embed_b via fp16 tensor path  (h0 = x_emb, no copy)
    to_half<<<1024, 256>>>(x, p_xh, (size_t)B_ * DIN);
    to_half<<<256, 256>>>(embed_w, p_ewh, (size_t)DH * DIN);
    gemm_f16<EPI_BIAS><<<NSM, 256, GSMEM>>>(
        p_xh, p_ewh, embed_b, DH, DIN, (B_ / 256) * (DH / 128), DH / 128,
        p_xemb, nullptr, nullptr, nullptr, 0.f);

    // hn0 = LN(h0 = xemb)
    layernorm_half<<<B_ / 8, 256>>>(p_xemb, ln_g, ln_b, p_hn);

    const int nt1 = (B_ / 256) * (DFF / 128);   // 512 tiles, nx=32
    const int nt2 = (B_ / 256) * (DH / 128);    // 128 tiles, nx=8

    const float* hc = p_xemb;                   // h0 aliases xemb (read-only)
    float* bufs[2] = {p_hA, p_hB};
    for (int s = 0; s < STEPS; s++) {
        float* hx = bufs[s & 1];
        gemm_f16<EPI_TANH><<<NSM, 256, GSMEM>>>(
            p_hn, p_W1h, b1, DFF, DH, nt1, DFF / 128,
            nullptr, p_hid, nullptr, nullptr, 0.f);
        gemm_f16<EPI_STEP><<<NSM, 256, GSMEM>>>(
            p_hid, p_W2h, b2, DH, DFF, nt2, DH / 128,
            hx, nullptr, hc, p_xemb, GAMMA_F);
        hc = hx;
        if (s + 1 < STEPS)
            layernorm_half<<<B_ / 8, 256>>>(hc, ln_g, ln_b, p_hn);
    }

    // out = h @ head_w^T + head_b via fp16 tensor path
    to_half<<<1024, 256>>>(hc, p_hf, (size_t)B_ * DH);
    to_half<<<128, 256>>>(head_w, p_hwh, (size_t)DOUT * DH);
    gemm_f16<EPI_BIAS><<<NSM, 256, GSMEM>>>(
        p_hf, p_hwh, head_b, DOUT, DH, (B_ / 256) * (DOUT / 128), DOUT / 128,
        out, nullptr, nullptr, nullptr, 0.f);
}

// round 17
// speedup vs baseline: 1.0987x; 1.0037x over previous
#include <cuda_runtime.h>
#include <cuda_fp16.h>
#include <math.h>
#include <cstddef>
#include <cstdint>

// ---------------- problem constants ----------------
#define B_    4096
#define DIN   512
#define DH    1024
#define DOUT  256
#define DFF   4096
#define STEPS 30
#define LN_EPSF 1e-5f
#define GAMMA_F 0.17677669529663687f   // 0.5*sqrt(64/512)
#define NSM   148
#define PI_NB 128

// ---------------- device scratch (no allocations allowed) ----------------
__device__ float g_xemb[(size_t)B_ * DH];
__device__ float g_hA[(size_t)B_ * DH];     // also: Gram B (4MB) during spectral
__device__ float g_hB[(size_t)B_ * DH];
__device__ __half g_W1h[(size_t)DFF * DH];
__device__ __half g_W2h[(size_t)DH * DFF];
__device__ __half g_hn[(size_t)B_ * DH];    // also: xh/ewh fp16 pre-loop
__device__ __half g_hid[(size_t)B_ * DFF];  // also: V fp16 during spectral; h-fp16 at end
__device__ float g_u[4096];
__device__ float g_v0[4096];
__device__ float g_v1[4096];
__device__ float g_t[4096];
__device__ float g_sig[2];
__device__ int   g_ictr[2];                 // [0]: power_iter ctr, [1]: loop LN barrier ctr

// ---------------- low-level helpers ----------------
__device__ __forceinline__ uint32_t smem_u32(const void* p) {
    uint32_t a;
    asm("{ .reg .u64 t; cvta.to.shared.u64 t, %1; cvt.u32.u64 %0, t; }" : "=r"(a) : "l"(p));
    return a;
}
__device__ __forceinline__ void cp_async16(uint32_t dst, const void* src) {
    asm volatile("cp.async.cg.shared.global [%0], [%1], 16;" :: "r"(dst), "l"(src) : "memory");
}
__device__ __forceinline__ void cp_commit() {
    asm volatile("cp.async.commit_group;" ::: "memory");
}
template<int N> __device__ __forceinline__ void cp_wait() {
    asm volatile("cp.async.wait_group %0;" :: "n"(N) : "memory");
}
__device__ __forceinline__ void ldm_x4(uint32_t addr, uint32_t* r) {
    asm volatile("ldmatrix.sync.aligned.m8n8.x4.shared.b16 {%0,%1,%2,%3}, [%4];"
        : "=r"(r[0]), "=r"(r[1]), "=r"(r[2]), "=r"(r[3]) : "r"(addr));
}
__device__ __forceinline__ void mma_f16(float* d, const uint32_t* a, const uint32_t* b) {
    asm volatile("mma.sync.aligned.m16n8k16.row.col.f32.f16.f16.f32 "
        "{%0,%1,%2,%3}, {%4,%5,%6,%7}, {%8,%9}, {%0,%1,%2,%3};"
        : "+f"(d[0]), "+f"(d[1]), "+f"(d[2]), "+f"(d[3])
        : "r"(a[0]), "r"(a[1]), "r"(a[2]), "r"(a[3]), "r"(b[0]), "r"(b[1]));
}
__device__ __forceinline__ float tanh_fast(float x) {
    float y;
    asm("tanh.approx.f32 %0, %1;" : "=f"(y) : "f"(x));
    return y;
}
__device__ __forceinline__ uint32_t sw_off(int r, int c) {
    return ((uint32_t)r << 6) + (uint32_t)((c ^ ((r >> 1) & 3)) << 4);
}
// monotone grid barrier (ctr zeroed once per replay before first use)
__device__ __forceinline__ void grid_bar(int* ctr, int gen, int nb) {
    __threadfence();
    __syncthreads();
    if (threadIdx.x == 0) {
        atomicAdd(ctr, 1);
        while (atomicAdd(ctr, 0) < gen * nb) { }
    }
    __syncthreads();
}

// ---------------- small kernels ----------------
__global__ void init_vec_kernel(float* v, size_t n, float val) {
    size_t i = (size_t)blockIdx.x * blockDim.x + threadIdx.x;
    if (i < n) v[i] = val;
}

// out[C][R] = fp16(in[R][C]^T)
__global__ void transpose_half(const float* __restrict__ in, __half* __restrict__ o,
                               int R, int C) {
    __shared__ float tile[32][33];
    int tx = threadIdx.x & 31, ty = threadIdx.x >> 5;
    int bx = blockIdx.x * 32;
    int by = blockIdx.y * 32;
    #pragma unroll
    for (int p = 0; p < 4; p++)
        tile[ty + p * 8][tx] = in[(size_t)(by + ty + p * 8) * C + bx + tx];
    __syncthreads();
    #pragma unroll
    for (int p = 0; p < 4; p++)
        o[(size_t)(bx + ty + p * 8) * R + by + tx] = __float2half_rn(tile[tx][ty + p * 8]);
}

// fp32 -> fp16 (float4 loads)
__global__ void to_half(const float* __restrict__ in, __half* __restrict__ o, size_t n) {
    size_t n4 = n >> 2;
    size_t stride = (size_t)gridDim.x * blockDim.x;
    const float4* in4 = reinterpret_cast<const float4*>(in);
    for (size_t i = (size_t)blockIdx.x * blockDim.x + threadIdx.x; i < n4; i += stride) {
        float4 w = in4[i];
        __half2 a, b;
        a.x = __float2half_rn(w.x); a.y = __float2half_rn(w.y);
        b.x = __float2half_rn(w.z); b.y = __float2half_rn(w.w);
        *reinterpret_cast<__half2*>(o + i * 4)     = a;
        *reinterpret_cast<__half2*>(o + i * 4 + 2) = b;
    }
}

// y[row] = dot(W[row,:], v)
__global__ void matvec_rows(const float* __restrict__ W, const float* __restrict__ v,
                            float* __restrict__ y, int C) {
    int row = blockIdx.x;
    const float4* Wr = reinterpret_cast<const float4*>(W + (size_t)row * C);
    const float4* v4 = reinterpret_cast<const float4*>(v);
    int C4 = C >> 2;
    float acc = 0.f;
    for (int j = threadIdx.x; j < C4; j += 256) {
        float4 a = Wr[j];
        float4 b = v4[j];
        acc += a.x * b.x + a.y * b.y + a.z * b.z + a.w * b.w;
    }
    __shared__ float sm[8];
    #pragma unroll
    for (int o = 16; o > 0; o >>= 1) acc += __shfl_down_sync(0xffffffffu, acc, o);
    if ((threadIdx.x & 31) == 0) sm[threadIdx.x >> 5] = acc;
    __syncthreads();
    if (threadIdx.x < 8) {
        float a = sm[threadIdx.x];
        #pragma unroll
        for (int o = 4; o > 0; o >>= 1) a += __shfl_down_sync(0xffu, a, o);
        if (threadIdx.x == 0) y[row] = a;
    }
}

// One-launch power iteration (see R16)
__global__ __launch_bounds__(256, 1) void power_iter(
    const float* __restrict__ B,
    float* b0, float* b1, float* b2,
    int n, int iters, int* ctr, int mode, float initval, float* sig) {

    float* buf[3] = {b0, b1, b2};
    int nb = gridDim.x;
    int warp = threadIdx.x >> 5, lane = threadIdx.x & 31;
    int row = blockIdx.x * 8 + warp;
    int gen = 0;

    if (initval != 0.f) {
        for (int i = blockIdx.x * blockDim.x + threadIdx.x; i < n; i += nb * blockDim.x)
            b0[i] = initval;
        gen++;
        grid_bar(ctr, gen, nb);
    }

    for (int k = 0; k < iters; k++) {
        const float* xc = buf[k % 3];
        float* yc = buf[(k + 1) % 3];
        const float4* Br = reinterpret_cast<const float4*>(B + (size_t)row * n);
        const float4* x4 = reinterpret_cast<const float4*>(xc);
        float acc = 0.f;
        for (int j = lane; j < (n >> 2); j += 32) {
            float4 a = Br[j], b = x4[j];
            acc += a.x * b.x + a.y * b.y + a.z * b.z + a.w * b.w;
        }
        #pragma unroll
        for (int o = 16; o > 0; o >>= 1) acc += __shfl_xor_sync(0xffffffffu, acc, o);
        if (lane == 0) yc[row] = acc;
        gen++;
        grid_bar(ctr, gen, nb);
    }

    if (blockIdx.x == 0) {
        const float* vb = buf[iters % 3];
        const float* va = buf[(iters + 2) % 3];
        const float* vc = buf[(iters + 1) % 3];
        float d1 = 0.f, d2 = 0.f;
        for (int i = threadIdx.x; i < n; i += blockDim.x) {
            float bi = vb[i];
            if (mode == 0) { d1 += bi * bi;     d2 += va[i] * bi; }
            else           { d1 += va[i] * bi;  d2 += vc[i] * bi; }
        }
        __shared__ float s1[8], s2[8];
        #pragma unroll
        for (int o = 16; o > 0; o >>= 1) {
            d1 += __shfl_xor_sync(0xffffffffu, d1, o);
            d2 += __shfl_xor_sync(0xffffffffu, d2, o);
        }
        if (lane == 0) { s1[warp] = d1; s2[warp] = d2; }
        __syncthreads();
        if (threadIdx.x < 8) {
            d1 = s1[threadIdx.x]; d2 = s2[threadIdx.x];
            #pragma unroll
            for (int o = 4; o > 0; o >>= 1) {
                d1 += __shfl_xor_sync(0xffu, d1, o);
                d2 += __shfl_xor_sync(0xffu, d2, o);
            }
            if (threadIdx.x == 0) sig[0] = sqrtf(d1 / d2);
        }
    }
}

// Wh = fp16(W / sigma)
__global__ void scale_half(const float* __restrict__ W, const float* __restrict__ sig,
                           __half* __restrict__ Wh, size_t n) {
    float inv = 1.0f / sig[0];
    size_t n4 = n >> 2;
    size_t stride = (size_t)gridDim.x * blockDim.x;
    const float4* W4 = reinterpret_cast<const float4*>(W);
    for (size_t i = (size_t)blockIdx.x * blockDim.x + threadIdx.x; i < n4; i += stride) {
        float4 w = W4[i];
        __half2 a, b;
        a.x = __float2half_rn(w.x * inv); a.y = __float2half_rn(w.y * inv);
        b.x = __float2half_rn(w.z * inv); b.y = __float2half_rn(w.w * inv);
        *reinterpret_cast<__half2*>(Wh + i * 4)     = a;
        *reinterpret_cast<__half2*>(Wh + i * 4 + 2) = b;
    }
}

// ---------------- standalone layernorm (h0 only): warp-per-row ----------------
__global__ void layernorm_half(const float* __restrict__ h,
                               const float* __restrict__ g, const float* __restrict__ b,
                               __half* __restrict__ o) {
    int row  = blockIdx.x * 8 + (threadIdx.x >> 5);
    int lane = threadIdx.x & 31;
    const float4* hr = reinterpret_cast<const float4*>(h + (size_t)row * DH);
    float4 xv[8];
    float s = 0.f, ss = 0.f;
    #pragma unroll
    for (int k = 0; k < 8; k++) {
        float4 v = hr[lane + k * 32];
        xv[k] = v;
        s  += v.x + v.y + v.z + v.w;
        ss += v.x * v.x + v.y * v.y + v.z * v.z + v.w * v.w;
    }
    #pragma unroll
    for (int off = 16; off > 0; off >>= 1) {
        s  += __shfl_xor_sync(0xffffffffu, s, off);
        ss += __shfl_xor_sync(0xffffffffu, ss, off);
    }
    float mu  = s * (1.0f / DH);
    float var = ss * (1.0f / DH) - mu * mu;
    float inv = rsqrtf(var + LN_EPSF);
    const float4* g4 = reinterpret_cast<const float4*>(g);
    const float4* b4 = reinterpret_cast<const float4*>(b);
    #pragma unroll
    for (int k = 0; k < 8; k++) {
        int j = lane + k * 32;
        float4 gv = g4[j];
        float4 bv = b4[j];
        float4 v = xv[k];
        __half2 o0, o1;
        o0.x = __float2half_rn((v.x - mu) * inv * gv.x + bv.x);
        o0.y = __float2half_rn((v.y - mu) * inv * gv.y + bv.y);
        o1.x = __float2half_rn((v.z - mu) * inv * gv.z + bv.z);
        o1.y = __float2half_rn((v.w - mu) * inv * gv.w + bv.w);
        *reinterpret_cast<__half2*>(o + (size_t)row * DH + j * 4)     = o0;
        *reinterpret_cast<__half2*>(o + (size_t)row * DH + j * 4 + 2) = o1;
    }
}

// ---------------- shared GEMM pieces ----------------
#define MSTAGES 4
#define ATILEB  (256 * 64)
#define WTILEB  (128 * 64)
#define STAGEB  (ATILEB + WTILEB)
#define GSMEM   (MSTAGES * STAGEB)       // 98304 B

#define EPI_BIAS 0
#define EPI_TANH 1
#define EPI_STEP 2

__device__ __forceinline__ void load_stage(
    uint32_t sbase, int buf, int k0,
    const __half* __restrict__ A, const __half* __restrict__ Wh,
    int bm, int bn, int K, int tid)
{
    uint32_t base = sbase + (uint32_t)buf * STAGEB;
    #pragma unroll
    for (int j = 0; j < 4; j++) {
        int c = tid + j * 256;
        int rr = c >> 2, c16 = c & 3;
        cp_async16(base + sw_off(rr, c16),
                   A + (size_t)(bm + rr) * K + k0 + c16 * 8);
    }
    #pragma unroll
    for (int j = 0; j < 2; j++) {
        int c = tid + j * 256;
        int rr = c >> 2, c16 = c & 3;
        cp_async16(base + (uint32_t)ATILEB + sw_off(rr, c16),
                   Wh + (size_t)(bn + rr) * K + k0 + c16 * 8);
    }
}

// ---------------- Gram kernel: single fp16 term, split-K, atomic accum ----------
__global__ __launch_bounds__(256, 1) void gram_f16(
    const __half* __restrict__ V,
    float* __restrict__ G, int N, int K, int nunits, int nx, int kchunks)
{
    extern __shared__ __align__(128) char smem[];
    uint32_t sb = smem_u32(smem);
    int tid = threadIdx.x, wid = tid >> 5, lane = tid & 31;
    int m0 = (wid >> 1) * 64, n0 = (wid & 1) * 64;
    int r16 = lane & 15, kh = lane >> 4;
    int g8 = lane >> 3, l8 = lane & 7;
    int qr = lane >> 2, qc = (lane & 3) * 2;

    for (int unit = blockIdx.x; unit < nunits; unit += gridDim.x) {
        int tile = unit >> 2, kid = unit & 3;
        int bm = (tile / nx) * 256, bn = (tile % nx) * 128;
        int kbase = kid * (kchunks << 5);

        float acc[4][8][4] = {};

        #pragma unroll
        for (int s = 0; s < MSTAGES - 1; s++) {
            load_stage(sb, s, kbase + (s << 5), V, V, bm, bn, K, tid);
            cp_commit();
        }

        for (int i = 0; i < kchunks; i++) {
            cp_wait<MSTAGES - 2>();
            __syncthreads();

            uint32_t st = sb + (uint32_t)(i & (MSTAGES - 1)) * STAGEB;
            #pragma unroll
            for (int ks = 0; ks < 2; ks++) {
                uint32_t a[4][4], w[4][4];
                #pragma unroll
                for (int mt = 0; mt < 4; mt++)
                    ldm_x4(st + sw_off(m0 + mt * 16 + r16, ks * 2 + kh), a[mt]);
                #pragma unroll
                for (int nh = 0; nh < 4; nh++)
                    ldm_x4(st + ATILEB +
                           sw_off(n0 + nh * 16 + (g8 >> 1) * 8 + l8, ks * 2 + (g8 & 1)),
                           w[nh]);
                #pragma unroll
                for (int mt = 0; mt < 4; mt++)
                    #pragma unroll
                    for (int nt = 0; nt < 8; nt++)
                        mma_f16(acc[mt][nt], a[mt], &w[nt >> 1][(nt & 1) * 2]);
            }

            int nxt = i + MSTAGES - 1;
            if (nxt < kchunks)
                load_stage(sb, nxt & (MSTAGES - 1), kbase + (nxt << 5), V, V, bm, bn, K, tid);
            cp_commit();
        }

        #pragma unroll
        for (int mt = 0; mt < 4; mt++) {
            #pragma unroll
            for (int nt = 0; nt < 8; nt++) {
                int c0 = bn + n0 + nt * 8 + qc;
                #pragma unroll
                for (int h = 0; h < 2; h++) {
                    int r = bm + m0 + mt * 16 + qr + h * 8;
                    size_t idx = (size_t)r * N + c0;
                    atomicAdd(&G[idx],     acc[mt][nt][h * 2 + 0]);
                    atomicAdd(&G[idx + 1], acc[mt][nt][h * 2 + 1]);
                }
            }
        }
        __syncthreads();
    }
}

// ---------------- gemm_tanh with optional fused LN phase-0 ----------------
// If hsrc != nullptr: phase0 computes hn = LN(hsrc) over strided rows, then
// grid barrier (ctr, gen), then the GEMM reads hn. grid MUST be NSM (co-resident).
__global__ __launch_bounds__(256, 1) void gemm_tanh_ln(
    const __half* __restrict__ A, const __half* __restrict__ Wh,
    const float* __restrict__ bias, int N, int K, int ntiles, int nx,
    __half* __restrict__ Ch,
    const float* __restrict__ hsrc, const float* __restrict__ lng,
    const float* __restrict__ lnb, __half* __restrict__ hn,
    int* ctr, int gen) {

    extern __shared__ __align__(128) char smem[];
    uint32_t sb = smem_u32(smem);
    int tid = threadIdx.x, wid = tid >> 5, lane = tid & 31;

    if (hsrc) {
        // phase 0: LN, warp-per-row, rows strided across the grid
        for (int row = blockIdx.x * 8 + wid; row < B_; row += gridDim.x * 8) {
            const float4* hr = reinterpret_cast<const float4*>(hsrc + (size_t)row * DH);
            float4 xv[8];
            float s = 0.f, ss = 0.f;
            #pragma unroll
            for (int k = 0; k < 8; k++) {
                float4 v = hr[lane + k * 32];
                xv[k] = v;
                s  += v.x + v.y + v.z + v.w;
                ss += v.x * v.x + v.y * v.y + v.z * v.z + v.w * v.w;
            }
            #pragma unroll
            for (int off = 16; off > 0; off >>= 1) {
                s  += __shfl_xor_sync(0xffffffffu, s, off);
                ss += __shfl_xor_sync(0xffffffffu, ss, off);
            }
            float mu  = s * (1.0f / DH);
            float var = ss * (1.0f / DH) - mu * mu;
            float inv = rsqrtf(var + LN_EPSF);
            const float4* g4 = reinterpret_cast<const float4*>(lng);
            const float4* b4 = reinterpret_cast<const float4*>(lnb);
            #pragma unroll
            for (int k = 0; k < 8; k++) {
                int j = lane + k * 32;
                float4 gv = g4[j];
                float4 bv = b4[j];
                float4 v = xv[k];
                __half2 o0, o1;
                o0.x = __float2half_rn((v.x - mu) * inv * gv.x + bv.x);
                o0.y = __float2half_rn((v.y - mu) * inv * gv.y + bv.y);
                o1.x = __float2half_rn((v.z - mu) * inv * gv.z + bv.z);
                o1.y = __float2half_rn((v.w - mu) * inv * gv.w + bv.w);
                *reinterpret_cast<__half2*>(hn + (size_t)row * DH + j * 4)     = o0;
                *reinterpret_cast<__half2*>(hn + (size_t)row * DH + j * 4 + 2) = o1;
            }
        }
        grid_bar(ctr, gen, gridDim.x);
    }

    int m0 = (wid >> 1) * 64, n0 = (wid & 1) * 64;
    int r16 = lane & 15, kh = lane >> 4;
    int g8 = lane >> 3, l8 = lane & 7;
    int qr = lane >> 2, qc = (lane & 3) * 2;
    const int nch = K >> 5;

    for (int tile = blockIdx.x; tile < ntiles; tile += gridDim.x) {
        int bm = (tile / nx) * 256, bn = (tile % nx) * 128;

        float acc[4][8][4] = {};

        #pragma unroll
        for (int s = 0; s < MSTAGES - 1; s++) {
            load_stage(sb, s, s << 5, A, Wh, bm, bn, K, tid);
            cp_commit();
        }

        for (int i = 0; i < nch; i++) {
            cp_wait<MSTAGES - 2>();
            __syncthreads();

            uint32_t st = sb + (uint32_t)(i & (MSTAGES - 1)) * STAGEB;
            #pragma unroll
            for (int ks = 0; ks < 2; ks++) {
                uint32_t a[4][4], w[4][4];
                #pragma unroll
                for (int mt = 0; mt < 4; mt++)
                    ldm_x4(st + sw_off(m0 + mt * 16 + r16, ks * 2 + kh), a[mt]);
                #pragma unroll
                for (int nh = 0; nh < 4; nh++)
                    ldm_x4(st + ATILEB +
                           sw_off(n0 + nh * 16 + (g8 >> 1) * 8 + l8, ks * 2 + (g8 & 1)),
                           w[nh]);
                #pragma unroll
                for (int mt = 0; mt < 4; mt++)
                    #pragma unroll
                    for (int nt = 0; nt < 8; nt++)
                        mma_f16(acc[mt][nt], a[mt], &w[nt >> 1][(nt & 1) * 2]);
            }

            int nxt = i + MSTAGES - 1;
            if (nxt < nch)
                load_stage(sb, nxt & (MSTAGES - 1), nxt << 5, A, Wh, bm, bn, K, tid);
            cp_commit();
        }

        #pragma unroll
        for (int mt = 0; mt < 4; mt++) {
            #pragma unroll
            for (int nt = 0; nt < 8; nt++) {
                int c0 = bn + n0 + nt * 8 + qc;
                float2 bz = *(const float2*)(bias + c0);
                #pragma unroll
                for (int h = 0; h < 2; h++) {
                    int r = bm + m0 + mt * 16 + qr + h * 8;
                    float v0 = acc[mt][nt][h * 2 + 0] + bz.x;
                    float v1 = acc[mt][nt][h * 2 + 1] + bz.y;
                    size_t idx = (size_t)r * N + c0;
                    __half2 hp;
                    hp.x = __float2half_rn(tanh_fast(v0));
                    hp.y = __float2half_rn(tanh_fast(v1));
                    *(__half2*)(Ch + idx) = hp;
                }
            }
        }
        __syncthreads();
    }
}

// ---------------- generic fp16 GEMM (bias / step epilogues) ----------------
template <int EPI>
__global__ __launch_bounds__(256, 1) void gemm_f16(
    const __half* __restrict__ A, const __half* __restrict__ Wh,
    const float* __restrict__ bias, int N, int K, int ntiles, int nx,
    float* __restrict__ Cf,
    const float* __restrict__ hprev, const float* __restrict__ xemb, float gamma) {

    extern __shared__ __align__(128) char smem[];
    uint32_t sb = smem_u32(smem);
    int tid = threadIdx.x, wid = tid >> 5, lane = tid & 31;
    int m0 = (wid >> 1) * 64, n0 = (wid & 1) * 64;
    int r16 = lane & 15, kh = lane >> 4;
    int g8 = lane >> 3, l8 = lane & 7;
    int qr = lane >> 2, qc = (lane & 3) * 2;
    const int nch = K >> 5;

    for (int tile = blockIdx.x; tile < ntiles; tile += gridDim.x) {
        int bm = (tile / nx) * 256, bn = (tile % nx) * 128;

        float acc[4][8][4] = {};

        #pragma unroll
        for (int s = 0; s < MSTAGES - 1; s++) {
            load_stage(sb, s, s << 5, A, Wh, bm, bn, K, tid);
            cp_commit();
        }

        for (int i = 0; i < nch; i++) {
            cp_wait<MSTAGES - 2>();
            __syncthreads();

            uint32_t st = sb + (uint32_t)(i & (MSTAGES - 1)) * STAGEB;
            #pragma unroll
            for (int ks = 0; ks < 2; ks++) {
                uint32_t a[4][4], w[4][4];
                #pragma unroll
                for (int mt = 0; mt < 4; mt++)
                    ldm_x4(st + sw_off(m0 + mt * 16 + r16, ks * 2 + kh), a[mt]);
                #pragma unroll
                for (int nh = 0; nh < 4; nh++)
                    ldm_x4(st + ATILEB +
                           sw_off(n0 + nh * 16 + (g8 >> 1) * 8 + l8, ks * 2 + (g8 & 1)),
                           w[nh]);
                #pragma unroll
                for (int mt = 0; mt < 4; mt++)
                    #pragma unroll
                    for (int nt = 0; nt < 8; nt++)
                        mma_f16(acc[mt][nt], a[mt], &w[nt >> 1][(nt & 1) * 2]);
            }

            int nxt = i + MSTAGES - 1;
            if (nxt < nch)
                load_stage(sb, nxt & (MSTAGES - 1), nxt << 5, A, Wh, bm, bn, K, tid);
            cp_commit();
        }

        #pragma unroll
        for (int mt = 0; mt < 4; mt++) {
            #pragma unroll
            for (int nt = 0; nt < 8; nt++) {
                int c0 = bn + n0 + nt * 8 + qc;
                float2 bz = *(const float2*)(bias + c0);
                #pragma unroll
                for (int h = 0; h < 2; h++) {
                    int r = bm + m0 + mt * 16 + qr + h * 8;
                    float v0 = acc[mt][nt][h * 2 + 0] + bz.x;
                    float v1 = acc[mt][nt][h * 2 + 1] + bz.y;
                    size_t idx = (size_t)r * N + c0;
                    if (EPI == EPI_STEP) {
                        float2 hp = *(const float2*)(hprev + idx);
                        float2 xe = *(const float2*)(xemb + idx);
                        float2 o;
                        o.x = (1.0f - gamma) * hp.x + gamma * (v0 + xe.x);
                        o.y = (1.0f - gamma) * hp.y + gamma * (v1 + xe.y);
                        *(float2*)(Cf + idx) = o;
                    } else {
                        float2 o; o.x = v0; o.y = v1;
                        *(float2*)(Cf + idx) = o;
                    }
                }
            }
        }
        __syncthreads();
    }
}

extern "C" void kernel_launch(void* const* d_in, const int* in_sizes, int n_in,
                              void* d_out, int out_size) {
    const float* x       = (const float*)d_in[0];
    const float* embed_w = (const float*)d_in[1];
    const float* embed_b = (const float*)d_in[2];
    const float* W1      = (const float*)d_in[3];
    const float* b1      = (const float*)d_in[4];
    const float* W2      = (const float*)d_in[5];
    const float* b2      = (const float*)d_in[6];
    const float* ln_g    = (const float*)d_in[7];
    const float* ln_b    = (const float*)d_in[8];
    const float* head_w  = (const float*)d_in[9];
    const float* head_b  = (const float*)d_in[10];
    float* out = (float*)d_out;

    float *p_xemb, *p_hA, *p_hB, *p_u, *p_v0, *p_v1, *p_t, *p_sig;
    int* p_ictr;
    __half *p_W1h, *p_W2h, *p_hn, *p_hid;
    cudaGetSymbolAddress((void**)&p_xemb, g_xemb);
    cudaGetSymbolAddress((void**)&p_hA, g_hA);
    cudaGetSymbolAddress((void**)&p_hB, g_hB);
    cudaGetSymbolAddress((void**)&p_u, g_u);
    cudaGetSymbolAddress((void**)&p_v0, g_v0);
    cudaGetSymbolAddress((void**)&p_v1, g_v1);
    cudaGetSymbolAddress((void**)&p_t, g_t);
    cudaGetSymbolAddress((void**)&p_sig, g_sig);
    cudaGetSymbolAddress((void**)&p_ictr, g_ictr);
    cudaGetSymbolAddress((void**)&p_W1h, g_W1h);
    cudaGetSymbolAddress((void**)&p_W2h, g_W2h);
    cudaGetSymbolAddress((void**)&p_hn, g_hn);
    cudaGetSymbolAddress((void**)&p_hid, g_hid);

    // scratch aliases
    float*  p_B   = p_hA;                        // 4MB Gram (pre-loop)
    __half* p_V   = p_hid;                       // 8MB V fp16 (pre-loop)
    __half* p_xh  = p_hn;                        // 4MB x fp16 (pre-hn0)
    __half* p_ewh = p_hn + (size_t)B_ * DIN;     // 1MB embed_w fp16 (pre-hn0)
    __half* p_hf  = p_hid;                       // h-final fp16 (post-loop)
    __half* p_hwh = p_hid + (size_t)B_ * DH;     // head_w fp16 (post-loop)

    cudaFuncSetAttribute(gemm_f16<EPI_BIAS>,
                         cudaFuncAttributeMaxDynamicSharedMemorySize, GSMEM);
    cudaFuncSetAttribute(gemm_f16<EPI_STEP>,
                         cudaFuncAttributeMaxDynamicSharedMemorySize, GSMEM);
    cudaFuncSetAttribute(gemm_tanh_ln,
                         cudaFuncAttributeMaxDynamicSharedMemorySize, GSMEM);
    cudaFuncSetAttribute(gram_f16,
                         cudaFuncAttributeMaxDynamicSharedMemorySize, GSMEM);

    // ===== spectral sigma for W1 (v-space: B = W1^T W1, single fp16 term) =====
    transpose_half<<<dim3(DH / 32, DFF / 32), 256>>>(W1, p_V, DFF, DH);
    init_vec_kernel<<<4096, 256>>>(p_B, (size_t)1024 * 1024, 0.f);
    gram_f16<<<NSM, 256, GSMEM>>>(p_V, p_B, 1024, DFF, 128, 8, 32);
    init_vec_kernel<<<1, 32>>>((float*)p_ictr, 1, 0.f);
    power_iter<<<PI_NB, 256>>>(p_B, p_u, p_v0, p_v1, 1024, 15, p_ictr, 0, 0.03125f, p_sig);

    // ===== spectral sigma for W2 (u-space: B' = W2 W2^T, single fp16 term) =====
    to_half<<<2048, 256>>>(W2, p_V, (size_t)DH * DFF);
    init_vec_kernel<<<4096, 256>>>(p_B, (size_t)1024 * 1024, 0.f);
    gram_f16<<<NSM, 256, GSMEM>>>(p_V, p_B, 1024, DFF, 128, 8, 32);
    init_vec_kernel<<<16, 256>>>(p_t, 4096, 0.015625f);
    matvec_rows<<<DH, 256>>>(W2, p_t, p_u, DFF);
    init_vec_kernel<<<1, 32>>>((float*)p_ictr, 1, 0.f);
    power_iter<<<PI_NB, 256>>>(p_B, p_u, p_v0, p_v1, 1024, 15, p_ictr, 1, 0.f, p_sig + 1);

    // fp16 weights (W / sigma)
    scale_half<<<2048, 256>>>(W1, p_sig, p_W1h, (size_t)DFF * DH);
    scale_half<<<2048, 256>>>(W2, p_sig + 1, p_W2h, (size_t)DH * DFF);

    // x_emb = x @ embed_w^T + embed_b via fp16 tensor path (h0 = x_emb)
    to_half<<<1024, 256>>>(x, p_xh, (size_t)B_ * DIN);
    to_half<<<256, 256>>>(embed_w, p_ewh, (size_t)DH * DIN);
    gemm_f16<EPI_BIAS><<<NSM, 256, GSMEM>>>(
        p_xh, p_ewh, embed_b, DH, DIN, (B_ / 256) * (DH / 128), DH / 128,
        p_xemb, nullptr, nullptr, 0.f);

    // hn0 = LN(h0 = xemb); zero loop-LN barrier counter
    layernorm_half<<<B_ / 8, 256>>>(p_xemb, ln_g, ln_b, p_hn);
    init_vec_kernel<<<1, 32>>>((float*)(p_ictr + 1), 1, 0.f);

    const int nt1 = (B_ / 256) * (DFF / 128);   // 512 tiles, nx=32
    const int nt2 = (B_ / 256) * (DH / 128);    // 128 tiles, nx=8

    const float* hc = p_xemb;
    float* bufs[2] = {p_hA, p_hB};
    for (int s = 0; s < STEPS; s++) {
        float* hx = bufs[s & 1];
        gemm_tanh_ln<<<NSM, 256, GSMEM>>>(
            p_hn, p_W1h, b1, DFF, DH, nt1, DFF / 128, p_hid,
            (s == 0) ? nullptr : hc, ln_g, ln_b, p_hn,
            p_ictr + 1, s);
        gemm_f16<EPI_STEP><<<NSM, 256, GSMEM>>>(
            p_hid, p_W2h, b2, DH, DFF, nt2, DH / 128,
            hx, hc, p_xemb, GAMMA_F);
        hc = hx;
    }

    // out = h @ head_w^T + head_b via fp16 tensor path
    to_half<<<1024, 256>>>(hc, p_hf, (size_t)B_ * DH);
    to_half<<<128, 256>>>(head_w, p_hwh, (size_t)DOUT * DH);
    gemm_f16<EPI_BIAS><<<NSM, 256, GSMEM>>>(
        p_hf, p_hwh, head_b, DOUT, DH, (B_ / 256) * (DOUT / 128), DOUT / 128,
        out, nullptr, nullptr, 0.f);
}